// round 6
// baseline (speedup 1.0000x reference)
#include <cuda_runtime.h>
#include <cuda_fp16.h>
#include <cstdint>

#define NN   50000
#define NE   800000
#define FIN  128
#define FHID 384
#define FOUT 256

// ----------------------------- scratch --------------------------------------
__device__ float  g_agg1[NN * FIN];            // 25.6 MB
__device__ float  g_x1[(size_t)NN * FHID];     // 76.8 MB
__device__ __half g_y_h[(size_t)NN * FOUT];    // 25.6 MB
__device__ __half g_feat_h[NN * FIN];          // 12.8 MB (features * out_norm, fp16)
__device__ int    g_deg[2 * NN];               // [0..NN)=deg_out, [NN..2NN)=deg_in
__device__ float  g_out_norm[NN];
__device__ float  g_in_norm[NN];
__device__ int    g_off[NN + 1];
__device__ int    g_cursor[NN];
__device__ int    g_csr_src[NE];

// ----------------------------- helpers --------------------------------------
__device__ __forceinline__ unsigned f2tf32(float x) {
    unsigned r;
    asm("cvt.rna.tf32.f32 %0, %1;" : "=r"(r) : "f"(x));
    return r;
}

__device__ __forceinline__ void mma_tf32(float& c0, float& c1, float& c2, float& c3,
                                         unsigned a0, unsigned a1, unsigned a2, unsigned a3,
                                         unsigned b0, unsigned b1) {
    asm volatile("mma.sync.aligned.m16n8k8.row.col.f32.tf32.tf32.f32 "
                 "{%0,%1,%2,%3}, {%4,%5,%6,%7}, {%8,%9}, {%0,%1,%2,%3};"
                 : "+f"(c0), "+f"(c1), "+f"(c2), "+f"(c3)
                 : "r"(a0), "r"(a1), "r"(a2), "r"(a3), "r"(b0), "r"(b1));
}

__device__ __forceinline__ __half2 bits2h(unsigned u) {
    return *reinterpret_cast<__half2*>(&u);
}

// ----------------------------- prelude kernels -------------------------------
__global__ void degree_kernel(const int* __restrict__ ei, int* __restrict__ deg) {
    int e = blockIdx.x * blockDim.x + threadIdx.x;
    if (e < NE) {
        atomicAdd(&deg[ei[e]], 1);            // deg_out
        atomicAdd(&deg[NN + ei[NE + e]], 1);  // deg_in
    }
}

// Single block: exclusive scan of deg_in -> off/cursor, plus both norms.
__global__ void scan_norm_kernel(const int* __restrict__ deg,
                                 int* __restrict__ off, int* __restrict__ cursor,
                                 float* __restrict__ onorm, float* __restrict__ inorm) {
    constexpr int T = 1024;
    constexpr int CHUNK = (NN + T - 1) / T;   // 49
    const int* din = deg + NN;
    __shared__ int ssum[T];
    int t = threadIdx.x;
    int base = t * CHUNK;
    int s = 0;
#pragma unroll 4
    for (int i = 0; i < CHUNK; i++) {
        int idx = base + i;
        if (idx < NN) s += din[idx];
    }
    ssum[t] = s;
    __syncthreads();
    for (int d = 1; d < T; d <<= 1) {
        int v = (t >= d) ? ssum[t - d] : 0;
        __syncthreads();
        if (t >= d) ssum[t] += v;
        __syncthreads();
    }
    int run = (t > 0) ? ssum[t - 1] : 0;
    for (int i = 0; i < CHUNK; i++) {
        int idx = base + i;
        if (idx < NN) {
            off[idx] = run;
            cursor[idx] = run;
            run += din[idx];
            onorm[idx] = rsqrtf((float)max(deg[idx], 1));
            inorm[idx] = rsqrtf((float)max(din[idx], 1));
        }
    }
    if (t == T - 1) off[NN] = NE;
}

// Counting-sort scatter + fp16 feature conversion (pre-scaled by out_norm).
__global__ void scatter_f2h_kernel(const int* __restrict__ ei,
                                   int* __restrict__ cursor,
                                   int* __restrict__ csr_src,
                                   const float* __restrict__ feat,
                                   const float* __restrict__ onorm,
                                   __half* __restrict__ feat_h) {
    int e = blockIdx.x * blockDim.x + threadIdx.x;
    if (e < NE) {
        int src = ei[e];
        int dst = ei[NE + e];
        int pos = atomicAdd(&cursor[dst], 1);
        csr_src[pos] = src;
    }
    // f2h: 1.6M uint2 elements over 800k threads (2 each)
    const int n4 = NN * (FIN / 4);
    int total = blockDim.x * gridDim.x;
    for (int i = e; i < n4; i += total) {
        int row = i >> 5;                     // FIN/4 = 32
        float sc = __ldg(&onorm[row]);
        float4 v = ((const float4*)feat)[i];
        __half2 h0 = __floats2half2_rn(v.x * sc, v.y * sc);
        __half2 h1 = __floats2half2_rn(v.z * sc, v.w * sc);
        ((uint2*)feat_h)[i] = make_uint2(*(unsigned*)&h0, *(unsigned*)&h1);
    }
}

// ----------------------------- gathers (MLP-unrolled) ------------------------
// agg1[n] = sum_{src in N(n)} feat_h[src]   (feat_h pre-scaled by out_norm)
__global__ void agg1_gather_kernel(const int* __restrict__ off,
                                   const int* __restrict__ csr_src,
                                   const __half* __restrict__ feat,
                                   float* __restrict__ agg) {
    int n = (blockIdx.x * blockDim.x + threadIdx.x) >> 5;
    if (n >= NN) return;
    int lane = threadIdx.x & 31;
    int beg = off[n], end = off[n + 1];
    float4 acc = make_float4(0.f, 0.f, 0.f, 0.f);
    for (int j = beg; j < end; j += 32) {
        int m = min(32, end - j);
        int s = (lane < m) ? __ldg(&csr_src[j + lane]) : 0;
        int k = 0;
        for (; k + 4 <= m; k += 4) {
            int s0 = __shfl_sync(0xffffffffu, s, k + 0);
            int s1 = __shfl_sync(0xffffffffu, s, k + 1);
            int s2 = __shfl_sync(0xffffffffu, s, k + 2);
            int s3 = __shfl_sync(0xffffffffu, s, k + 3);
            uint2 u0 = __ldg((const uint2*)(feat + (size_t)s0 * FIN + lane * 4));
            uint2 u1 = __ldg((const uint2*)(feat + (size_t)s1 * FIN + lane * 4));
            uint2 u2 = __ldg((const uint2*)(feat + (size_t)s2 * FIN + lane * 4));
            uint2 u3 = __ldg((const uint2*)(feat + (size_t)s3 * FIN + lane * 4));
            float2 a, b;
            a = __half22float2(bits2h(u0.x)); b = __half22float2(bits2h(u0.y));
            acc.x += a.x; acc.y += a.y; acc.z += b.x; acc.w += b.y;
            a = __half22float2(bits2h(u1.x)); b = __half22float2(bits2h(u1.y));
            acc.x += a.x; acc.y += a.y; acc.z += b.x; acc.w += b.y;
            a = __half22float2(bits2h(u2.x)); b = __half22float2(bits2h(u2.y));
            acc.x += a.x; acc.y += a.y; acc.z += b.x; acc.w += b.y;
            a = __half22float2(bits2h(u3.x)); b = __half22float2(bits2h(u3.y));
            acc.x += a.x; acc.y += a.y; acc.z += b.x; acc.w += b.y;
        }
        for (; k < m; k++) {
            int ss = __shfl_sync(0xffffffffu, s, k);
            uint2 u = __ldg((const uint2*)(feat + (size_t)ss * FIN + lane * 4));
            float2 a = __half22float2(bits2h(u.x));
            float2 b = __half22float2(bits2h(u.y));
            acc.x += a.x; acc.y += a.y; acc.z += b.x; acc.w += b.y;
        }
    }
    *(float4*)(agg + (size_t)n * FIN + lane * 4) = acc;
}

// out[n] = inorm[n] * sum_{src in N(n)} y_h[src] + b2
__global__ void agg2_gather_kernel(const int* __restrict__ off,
                                   const int* __restrict__ csr_src,
                                   const __half* __restrict__ y,
                                   const float* __restrict__ inorm,
                                   const float* __restrict__ b2,
                                   float* __restrict__ out) {
    int n = (blockIdx.x * blockDim.x + threadIdx.x) >> 5;
    if (n >= NN) return;
    int lane = threadIdx.x & 31;
    int beg = off[n], end = off[n + 1];
    float acc[8] = {0.f, 0.f, 0.f, 0.f, 0.f, 0.f, 0.f, 0.f};
    for (int j = beg; j < end; j += 32) {
        int m = min(32, end - j);
        int s = (lane < m) ? __ldg(&csr_src[j + lane]) : 0;
        int k = 0;
        for (; k + 2 <= m; k += 2) {
            int s0 = __shfl_sync(0xffffffffu, s, k + 0);
            int s1 = __shfl_sync(0xffffffffu, s, k + 1);
            uint4 u0 = __ldg((const uint4*)(y + (size_t)s0 * FOUT + lane * 8));
            uint4 u1 = __ldg((const uint4*)(y + (size_t)s1 * FOUT + lane * 8));
            float2 f;
            f = __half22float2(bits2h(u0.x)); acc[0] += f.x; acc[1] += f.y;
            f = __half22float2(bits2h(u0.y)); acc[2] += f.x; acc[3] += f.y;
            f = __half22float2(bits2h(u0.z)); acc[4] += f.x; acc[5] += f.y;
            f = __half22float2(bits2h(u0.w)); acc[6] += f.x; acc[7] += f.y;
            f = __half22float2(bits2h(u1.x)); acc[0] += f.x; acc[1] += f.y;
            f = __half22float2(bits2h(u1.y)); acc[2] += f.x; acc[3] += f.y;
            f = __half22float2(bits2h(u1.z)); acc[4] += f.x; acc[5] += f.y;
            f = __half22float2(bits2h(u1.w)); acc[6] += f.x; acc[7] += f.y;
        }
        for (; k < m; k++) {
            int ss = __shfl_sync(0xffffffffu, s, k);
            uint4 u = __ldg((const uint4*)(y + (size_t)ss * FOUT + lane * 8));
            float2 f;
            f = __half22float2(bits2h(u.x)); acc[0] += f.x; acc[1] += f.y;
            f = __half22float2(bits2h(u.y)); acc[2] += f.x; acc[3] += f.y;
            f = __half22float2(bits2h(u.z)); acc[4] += f.x; acc[5] += f.y;
            f = __half22float2(bits2h(u.w)); acc[6] += f.x; acc[7] += f.y;
        }
    }
    float sc = __ldg(&inorm[n]);
    float4 bb0 = *(const float4*)(b2 + lane * 8);
    float4 bb1 = *(const float4*)(b2 + lane * 8 + 4);
    float4 o0, o1;
    o0.x = acc[0] * sc + bb0.x; o0.y = acc[1] * sc + bb0.y;
    o0.z = acc[2] * sc + bb0.z; o0.w = acc[3] * sc + bb0.w;
    o1.x = acc[4] * sc + bb1.x; o1.y = acc[5] * sc + bb1.y;
    o1.z = acc[6] * sc + bb1.z; o1.w = acc[7] * sc + bb1.w;
    float* orow = out + (size_t)n * FOUT + lane * 8;
    *(float4*)orow = o0;
    *(float4*)(orow + 4) = o1;
}

// ----------------------------- tf32 tensor GEMM (round-4 proven version) -----
// C = epi( (A[M,K] @ B[K,N]) * rowscale[row] (+ bias) (relu) ), C fp32 or fp16.
// BM=128, BN=64, BK=32; 256 threads = 8 warps (4 M x 2 N), warp tile 32x32.
// Double-buffered smem + register prefetch: one barrier per K-tile.
template<bool RELU, bool HAS_BIAS, bool OUT_HALF>
__global__ __launch_bounds__(256)
void gemm_tf32_kernel(const float* __restrict__ A, const float* __restrict__ B,
                      void* __restrict__ Cv,
                      const float* __restrict__ rowscale,
                      const float* __restrict__ bias,
                      int M, int N, int K) {
    constexpr int BM = 128, BN = 64, BK = 32;
    __shared__ unsigned As[2][BM][BK + 4];
    __shared__ unsigned Bs[2][BK][BN + 4];

    const int tid  = threadIdx.x;
    const int warp = tid >> 5;
    const int lane = tid & 31;
    const int wm = warp & 3;
    const int wn = warp >> 2;
    const int gid  = lane >> 2;
    const int tig  = lane & 3;

    const int brow0 = blockIdx.y * BM;
    const int bcol0 = blockIdx.x * BN;

    float acc[2][4][4];
#pragma unroll
    for (int mt = 0; mt < 2; mt++)
#pragma unroll
        for (int nt = 0; nt < 4; nt++)
#pragma unroll
            for (int f = 0; f < 4; f++) acc[mt][nt][f] = 0.f;

    float4 ra[4];
    float4 rb[2];

    auto load_tile = [&](int k0) {
#pragma unroll
        for (int l = 0; l < 4; l++) {
            int idx = tid + l * 256;
            int r   = idx >> 3;
            int c4  = idx & 7;
            int grow = brow0 + r;
            ra[l] = make_float4(0.f, 0.f, 0.f, 0.f);
            if (grow < M)
                ra[l] = *(const float4*)(A + (size_t)grow * K + k0 + c4 * 4);
        }
#pragma unroll
        for (int l = 0; l < 2; l++) {
            int idx = tid + l * 256;
            int kr  = idx >> 4;
            int nc4 = idx & 15;
            rb[l] = *(const float4*)(B + (size_t)(k0 + kr) * N + bcol0 + nc4 * 4);
        }
    };

    load_tile(0);
    int buf = 0;

    for (int k0 = 0; k0 < K; k0 += BK) {
#pragma unroll
        for (int l = 0; l < 4; l++) {
            int idx = tid + l * 256;
            int r   = idx >> 3;
            int c4  = idx & 7;
            As[buf][r][c4 * 4 + 0] = f2tf32(ra[l].x);
            As[buf][r][c4 * 4 + 1] = f2tf32(ra[l].y);
            As[buf][r][c4 * 4 + 2] = f2tf32(ra[l].z);
            As[buf][r][c4 * 4 + 3] = f2tf32(ra[l].w);
        }
#pragma unroll
        for (int l = 0; l < 2; l++) {
            int idx = tid + l * 256;
            int kr  = idx >> 4;
            int nc4 = idx & 15;
            Bs[buf][kr][nc4 * 4 + 0] = f2tf32(rb[l].x);
            Bs[buf][kr][nc4 * 4 + 1] = f2tf32(rb[l].y);
            Bs[buf][kr][nc4 * 4 + 2] = f2tf32(rb[l].z);
            Bs[buf][kr][nc4 * 4 + 3] = f2tf32(rb[l].w);
        }
        __syncthreads();

        if (k0 + BK < K) load_tile(k0 + BK);

#pragma unroll
        for (int ks = 0; ks < BK; ks += 8) {
            unsigned a[2][4];
#pragma unroll
            for (int mt = 0; mt < 2; mt++) {
                int r = wm * 32 + mt * 16 + gid;
                a[mt][0] = As[buf][r][ks + tig];
                a[mt][1] = As[buf][r + 8][ks + tig];
                a[mt][2] = As[buf][r][ks + 4 + tig];
                a[mt][3] = As[buf][r + 8][ks + 4 + tig];
            }
            unsigned b[4][2];
#pragma unroll
            for (int nt = 0; nt < 4; nt++) {
                int n = wn * 32 + nt * 8 + gid;
                b[nt][0] = Bs[buf][ks + tig][n];
                b[nt][1] = Bs[buf][ks + 4 + tig][n];
            }
#pragma unroll
            for (int mt = 0; mt < 2; mt++)
#pragma unroll
                for (int nt = 0; nt < 4; nt++)
                    mma_tf32(acc[mt][nt][0], acc[mt][nt][1],
                             acc[mt][nt][2], acc[mt][nt][3],
                             a[mt][0], a[mt][1], a[mt][2], a[mt][3],
                             b[nt][0], b[nt][1]);
        }
        buf ^= 1;
    }

#pragma unroll
    for (int mt = 0; mt < 2; mt++) {
        int r0 = brow0 + wm * 32 + mt * 16 + gid;
        int r1 = r0 + 8;
        float rs0 = (r0 < M) ? __ldg(&rowscale[r0]) : 0.f;
        float rs1 = (r1 < M) ? __ldg(&rowscale[r1]) : 0.f;
#pragma unroll
        for (int nt = 0; nt < 4; nt++) {
            int c = bcol0 + wn * 32 + nt * 8 + 2 * tig;
            float2 bb = make_float2(0.f, 0.f);
            if (HAS_BIAS) bb = *(const float2*)(bias + c);
            float2 o0, o1;
            o0.x = acc[mt][nt][0] * rs0 + bb.x;
            o0.y = acc[mt][nt][1] * rs0 + bb.y;
            o1.x = acc[mt][nt][2] * rs1 + bb.x;
            o1.y = acc[mt][nt][3] * rs1 + bb.y;
            if (RELU) {
                o0.x = fmaxf(o0.x, 0.f); o0.y = fmaxf(o0.y, 0.f);
                o1.x = fmaxf(o1.x, 0.f); o1.y = fmaxf(o1.y, 0.f);
            }
            if (OUT_HALF) {
                __half* C = (__half*)Cv;
                if (r0 < M) *(__half2*)(C + (size_t)r0 * N + c) = __floats2half2_rn(o0.x, o0.y);
                if (r1 < M) *(__half2*)(C + (size_t)r1 * N + c) = __floats2half2_rn(o1.x, o1.y);
            } else {
                float* C = (float*)Cv;
                if (r0 < M) *(float2*)(C + (size_t)r0 * N + c) = o0;
                if (r1 < M) *(float2*)(C + (size_t)r1 * N + c) = o1;
            }
        }
    }
}

// ----------------------------- launch ---------------------------------------
extern "C" void kernel_launch(void* const* d_in, const int* in_sizes, int n_in,
                              void* d_out, int out_size) {
    const float *features = nullptr, *W1 = nullptr, *b1 = nullptr,
                *W2 = nullptr, *b2 = nullptr;
    const int* ei = nullptr;
    for (int i = 0; i < n_in; i++) {
        switch (in_sizes[i]) {
            case NN * FIN:      features = (const float*)d_in[i]; break;
            case FIN * FHID:    W1 = (const float*)d_in[i]; break;
            case FHID:          b1 = (const float*)d_in[i]; break;
            case FHID * FOUT:   W2 = (const float*)d_in[i]; break;
            case FOUT:          b2 = (const float*)d_in[i]; break;
            case 2 * NE:        ei = (const int*)d_in[i]; break;
            default: break;
        }
    }
    float* out = (float*)d_out;

    float *agg1, *x1, *onorm, *inorm;
    __half *y_h, *feat_h;
    int *deg, *off, *cursor, *csr_src;
    cudaGetSymbolAddress((void**)&agg1,    g_agg1);
    cudaGetSymbolAddress((void**)&x1,      g_x1);
    cudaGetSymbolAddress((void**)&y_h,     g_y_h);
    cudaGetSymbolAddress((void**)&feat_h,  g_feat_h);
    cudaGetSymbolAddress((void**)&onorm,   g_out_norm);
    cudaGetSymbolAddress((void**)&inorm,   g_in_norm);
    cudaGetSymbolAddress((void**)&deg,     g_deg);
    cudaGetSymbolAddress((void**)&off,     g_off);
    cudaGetSymbolAddress((void**)&cursor,  g_cursor);
    cudaGetSymbolAddress((void**)&csr_src, g_csr_src);

    const int T = 256;

    // [memset node, not a kernel] zero degree counters
    cudaMemsetAsync(deg, 0, 2 * NN * sizeof(int));
    // [k1] degrees
    degree_kernel<<<(NE + T - 1) / T, T>>>(ei, deg);
    // [k2] scan + norms (single block)
    scan_norm_kernel<<<1, 1024>>>(deg, off, cursor, onorm, inorm);
    // [k3] counting-sort scatter + scaled fp16 feature conversion
    scatter_f2h_kernel<<<(NE + T - 1) / T, T>>>(ei, cursor, csr_src,
                                                features, onorm, feat_h);
    // [k4] agg1 = gather(feat_h)   <-- profiled launch
    {
        long long threads = (long long)NN * 32;
        agg1_gather_kernel<<<(unsigned)((threads + T - 1) / T), T>>>(
            off, csr_src, feat_h, agg1);
    }
    // [k5] x1 = relu( inorm[row] * (agg1 @ W1) + b1 )
    {
        dim3 grid(FHID / 64, (NN + 127) / 128);
        gemm_tf32_kernel<true, true, false><<<grid, 256>>>(agg1, W1, x1, inorm, b1,
                                                           NN, FHID, FIN);
    }
    // [k6] y_h = fp16( onorm[row] * (x1 @ W2) )
    {
        dim3 grid(FOUT / 64, (NN + 127) / 128);
        gemm_tf32_kernel<false, false, true><<<grid, 256>>>(x1, W2, y_h, onorm, nullptr,
                                                            NN, FOUT, FHID);
    }
    // [k7] out = inorm[row] * gather(y_h) + b2
    {
        long long threads = (long long)NN * 32;
        agg2_gather_kernel<<<(unsigned)((threads + T - 1) / T), T>>>(
            off, csr_src, y_h, inorm, b2, out);
    }
}

// round 7
// speedup vs baseline: 2.0095x; 2.0095x over previous
#include <cuda_runtime.h>
#include <cuda_fp16.h>
#include <cstdint>

#define NN   50000
#define NE   800000
#define FIN  128
#define FHID 384
#define FOUT 256
#define NB   196          // ceil(NN/256) scan blocks

// ----------------------------- scratch --------------------------------------
__device__ __half g_agg1h[NN * FIN];             // 12.8 MB (fp16 agg1)
__device__ __half g_x1h[(size_t)NN * FHID];      // 38.4 MB (fp16 x1)
__device__ __half g_y_h[(size_t)NN * FOUT];      // 25.6 MB
__device__ __half g_feat_h[NN * FIN];            // 12.8 MB (features * out_norm)
__device__ __half g_w1t[FHID * FIN];             // W1^T fp16 [384][128]
__device__ __half g_w2t[FOUT * FHID];            // W2^T fp16 [256][384]
__device__ int    g_deg[2 * NN];                 // [0..NN)=deg_out, [NN..)=deg_in
__device__ float  g_out_norm[NN];
__device__ float  g_in_norm[NN];
__device__ int    g_off[NN + 1];
__device__ int    g_cursor[NN];
__device__ int    g_csr_src[NE];
__device__ int    g_incl[NN];                    // per-element inclusive prefix
__device__ int    g_bsum[256];
__device__ int    g_bpre[256];

// ----------------------------- helpers --------------------------------------
__device__ __forceinline__ void ldsm_x4(unsigned& r0, unsigned& r1,
                                        unsigned& r2, unsigned& r3, unsigned addr) {
    asm volatile("ldmatrix.sync.aligned.m8n8.x4.shared.b16 {%0,%1,%2,%3}, [%4];"
                 : "=r"(r0), "=r"(r1), "=r"(r2), "=r"(r3) : "r"(addr));
}

__device__ __forceinline__ void mma_f16(float& c0, float& c1, float& c2, float& c3,
                                        unsigned a0, unsigned a1, unsigned a2, unsigned a3,
                                        unsigned b0, unsigned b1) {
    asm volatile("mma.sync.aligned.m16n8k16.row.col.f32.f16.f16.f32 "
                 "{%0,%1,%2,%3}, {%4,%5,%6,%7}, {%8,%9}, {%0,%1,%2,%3};"
                 : "+f"(c0), "+f"(c1), "+f"(c2), "+f"(c3)
                 : "r"(a0), "r"(a1), "r"(a2), "r"(a3), "r"(b0), "r"(b1));
}

__device__ __forceinline__ __half2 bits2h(unsigned u) {
    return *reinterpret_cast<__half2*>(&u);
}

// ----------------------------- prelude kernels -------------------------------
// W1^T, W2^T in fp16 (one-time per call; tiny)
__global__ void wconv_kernel(const float* __restrict__ W1, const float* __restrict__ W2,
                             __half* __restrict__ w1t, __half* __restrict__ w2t) {
    int i = blockIdx.x * blockDim.x + threadIdx.x;
    const int T1 = FHID * FIN;
    if (i < T1) {
        int n = i / FIN, k = i % FIN;
        w1t[i] = __float2half(W1[k * FHID + n]);
    }
    const int T2 = FOUT * FHID;
    if (i < T2) {
        int n = i / FHID, k = i % FHID;
        w2t[i] = __float2half(W2[k * FOUT + n]);
    }
}

__global__ void degree_kernel(const int* __restrict__ ei, int* __restrict__ deg) {
    int e = blockIdx.x * blockDim.x + threadIdx.x;
    if (e < NE) {
        atomicAdd(&deg[ei[e]], 1);
        atomicAdd(&deg[NN + ei[NE + e]], 1);
    }
}

// scan phase 1: per-block inclusive scan of deg_in, write incl + block sums
__global__ void scan1_kernel(const int* __restrict__ deg,
                             int* __restrict__ incl, int* __restrict__ bsum) {
    __shared__ int sh[256];
    int t = threadIdx.x;
    int i = blockIdx.x * 256 + t;
    int v = (i < NN) ? deg[NN + i] : 0;
    sh[t] = v;
    __syncthreads();
#pragma unroll
    for (int d = 1; d < 256; d <<= 1) {
        int x = (t >= d) ? sh[t - d] : 0;
        __syncthreads();
        if (t >= d) sh[t] += x;
        __syncthreads();
    }
    if (i < NN) incl[i] = sh[t];
    if (t == 255) bsum[blockIdx.x] = sh[255];
}

// scan phase 2: exclusive scan of block sums (single block)
__global__ void scan2_kernel(const int* __restrict__ bsum, int* __restrict__ bpre) {
    __shared__ int sh[256];
    int t = threadIdx.x;
    int v = (t < NB) ? bsum[t] : 0;
    sh[t] = v;
    __syncthreads();
#pragma unroll
    for (int d = 1; d < 256; d <<= 1) {
        int x = (t >= d) ? sh[t - d] : 0;
        __syncthreads();
        if (t >= d) sh[t] += x;
        __syncthreads();
    }
    bpre[t] = sh[t] - v;   // exclusive
}

// scan phase 3: final coalesced writes of off/cursor/norms
__global__ void scan3_kernel(const int* __restrict__ deg,
                             const int* __restrict__ incl, const int* __restrict__ bpre,
                             int* __restrict__ off, int* __restrict__ cursor,
                             float* __restrict__ onorm, float* __restrict__ inorm) {
    int i = blockIdx.x * 256 + threadIdx.x;
    if (i < NN) {
        int din = deg[NN + i];
        int excl = bpre[blockIdx.x] + incl[i] - din;
        off[i] = excl;
        cursor[i] = excl;
        onorm[i] = rsqrtf((float)max(deg[i], 1));
        inorm[i] = rsqrtf((float)max(din, 1));
    }
    if (i == 0) off[NN] = NE;
}

// counting-sort scatter + fp16 feature conversion (pre-scaled by out_norm)
__global__ void scatter_f2h_kernel(const int* __restrict__ ei,
                                   int* __restrict__ cursor,
                                   int* __restrict__ csr_src,
                                   const float* __restrict__ feat,
                                   const float* __restrict__ onorm,
                                   __half* __restrict__ feat_h) {
    int e = blockIdx.x * blockDim.x + threadIdx.x;
    if (e < NE) {
        int src = ei[e];
        int dst = ei[NE + e];
        int pos = atomicAdd(&cursor[dst], 1);
        csr_src[pos] = src;
    }
    const int n4 = NN * (FIN / 4);
    int total = blockDim.x * gridDim.x;
    for (int i = e; i < n4; i += total) {
        int row = i >> 5;
        float sc = __ldg(&onorm[row]);
        float4 v = ((const float4*)feat)[i];
        __half2 h0 = __floats2half2_rn(v.x * sc, v.y * sc);
        __half2 h1 = __floats2half2_rn(v.z * sc, v.w * sc);
        ((uint2*)feat_h)[i] = make_uint2(*(unsigned*)&h0, *(unsigned*)&h1);
    }
}

// ----------------------------- gathers ---------------------------------------
// agg1_h[n] = fp16( sum_{src in N(n)} feat_h[src] )
__global__ void agg1_gather_kernel(const int* __restrict__ off,
                                   const int* __restrict__ csr_src,
                                   const __half* __restrict__ feat,
                                   __half* __restrict__ aggh) {
    int n = (blockIdx.x * blockDim.x + threadIdx.x) >> 5;
    if (n >= NN) return;
    int lane = threadIdx.x & 31;
    int beg = off[n], end = off[n + 1];
    float4 acc = make_float4(0.f, 0.f, 0.f, 0.f);
    for (int j = beg; j < end; j += 32) {
        int m = min(32, end - j);
        int s = (lane < m) ? __ldg(&csr_src[j + lane]) : 0;
        int k = 0;
        for (; k + 4 <= m; k += 4) {
            int s0 = __shfl_sync(0xffffffffu, s, k + 0);
            int s1 = __shfl_sync(0xffffffffu, s, k + 1);
            int s2 = __shfl_sync(0xffffffffu, s, k + 2);
            int s3 = __shfl_sync(0xffffffffu, s, k + 3);
            uint2 u0 = __ldg((const uint2*)(feat + (size_t)s0 * FIN + lane * 4));
            uint2 u1 = __ldg((const uint2*)(feat + (size_t)s1 * FIN + lane * 4));
            uint2 u2 = __ldg((const uint2*)(feat + (size_t)s2 * FIN + lane * 4));
            uint2 u3 = __ldg((const uint2*)(feat + (size_t)s3 * FIN + lane * 4));
            float2 a, b;
            a = __half22float2(bits2h(u0.x)); b = __half22float2(bits2h(u0.y));
            acc.x += a.x; acc.y += a.y; acc.z += b.x; acc.w += b.y;
            a = __half22float2(bits2h(u1.x)); b = __half22float2(bits2h(u1.y));
            acc.x += a.x; acc.y += a.y; acc.z += b.x; acc.w += b.y;
            a = __half22float2(bits2h(u2.x)); b = __half22float2(bits2h(u2.y));
            acc.x += a.x; acc.y += a.y; acc.z += b.x; acc.w += b.y;
            a = __half22float2(bits2h(u3.x)); b = __half22float2(bits2h(u3.y));
            acc.x += a.x; acc.y += a.y; acc.z += b.x; acc.w += b.y;
        }
        for (; k < m; k++) {
            int ss = __shfl_sync(0xffffffffu, s, k);
            uint2 u = __ldg((const uint2*)(feat + (size_t)ss * FIN + lane * 4));
            float2 a = __half22float2(bits2h(u.x));
            float2 b = __half22float2(bits2h(u.y));
            acc.x += a.x; acc.y += a.y; acc.z += b.x; acc.w += b.y;
        }
    }
    __half2 h0 = __floats2half2_rn(acc.x, acc.y);
    __half2 h1 = __floats2half2_rn(acc.z, acc.w);
    ((uint2*)(aggh + (size_t)n * FIN))[lane] = make_uint2(*(unsigned*)&h0, *(unsigned*)&h1);
}

// out[n] = inorm[n] * sum_{src in N(n)} y_h[src] + b2
__global__ void agg2_gather_kernel(const int* __restrict__ off,
                                   const int* __restrict__ csr_src,
                                   const __half* __restrict__ y,
                                   const float* __restrict__ inorm,
                                   const float* __restrict__ b2,
                                   float* __restrict__ out) {
    int n = (blockIdx.x * blockDim.x + threadIdx.x) >> 5;
    if (n >= NN) return;
    int lane = threadIdx.x & 31;
    int beg = off[n], end = off[n + 1];
    float acc[8] = {0.f, 0.f, 0.f, 0.f, 0.f, 0.f, 0.f, 0.f};
    for (int j = beg; j < end; j += 32) {
        int m = min(32, end - j);
        int s = (lane < m) ? __ldg(&csr_src[j + lane]) : 0;
        int k = 0;
        for (; k + 2 <= m; k += 2) {
            int s0 = __shfl_sync(0xffffffffu, s, k + 0);
            int s1 = __shfl_sync(0xffffffffu, s, k + 1);
            uint4 u0 = __ldg((const uint4*)(y + (size_t)s0 * FOUT + lane * 8));
            uint4 u1 = __ldg((const uint4*)(y + (size_t)s1 * FOUT + lane * 8));
            float2 f;
            f = __half22float2(bits2h(u0.x)); acc[0] += f.x; acc[1] += f.y;
            f = __half22float2(bits2h(u0.y)); acc[2] += f.x; acc[3] += f.y;
            f = __half22float2(bits2h(u0.z)); acc[4] += f.x; acc[5] += f.y;
            f = __half22float2(bits2h(u0.w)); acc[6] += f.x; acc[7] += f.y;
            f = __half22float2(bits2h(u1.x)); acc[0] += f.x; acc[1] += f.y;
            f = __half22float2(bits2h(u1.y)); acc[2] += f.x; acc[3] += f.y;
            f = __half22float2(bits2h(u1.z)); acc[4] += f.x; acc[5] += f.y;
            f = __half22float2(bits2h(u1.w)); acc[6] += f.x; acc[7] += f.y;
        }
        for (; k < m; k++) {
            int ss = __shfl_sync(0xffffffffu, s, k);
            uint4 u = __ldg((const uint4*)(y + (size_t)ss * FOUT + lane * 8));
            float2 f;
            f = __half22float2(bits2h(u.x)); acc[0] += f.x; acc[1] += f.y;
            f = __half22float2(bits2h(u.y)); acc[2] += f.x; acc[3] += f.y;
            f = __half22float2(bits2h(u.z)); acc[4] += f.x; acc[5] += f.y;
            f = __half22float2(bits2h(u.w)); acc[6] += f.x; acc[7] += f.y;
        }
    }
    float sc = __ldg(&inorm[n]);
    float4 bb0 = *(const float4*)(b2 + lane * 8);
    float4 bb1 = *(const float4*)(b2 + lane * 8 + 4);
    float4 o0, o1;
    o0.x = acc[0] * sc + bb0.x; o0.y = acc[1] * sc + bb0.y;
    o0.z = acc[2] * sc + bb0.z; o0.w = acc[3] * sc + bb0.w;
    o1.x = acc[4] * sc + bb1.x; o1.y = acc[5] * sc + bb1.y;
    o1.z = acc[6] * sc + bb1.z; o1.w = acc[7] * sc + bb1.w;
    float* orow = out + (size_t)n * FOUT + lane * 8;
    *(float4*)orow = o0;
    *(float4*)(orow + 4) = o1;
}

// ----------------------------- fp16 tensor GEMM -------------------------------
// C[M,N](fp16) = epi( (A[M,K] @ Bt[N,K]^T) * rowscale[row] (+bias) (relu) )
// A fp16 row-major [M][K]; Bt fp16 row-major [N][K] (i.e. B transposed).
// BM=128, BN=64, BK=32; 8 warps (4M x 2N), warp tile 32x32.
// mma.m16n8k16 fp16, ldmatrix fragment loads; smem row stride 40 halves
// (conflict-free ldmatrix). Double-buffered, 1 barrier per K-tile.
template<bool RELU, bool HAS_BIAS>
__global__ __launch_bounds__(256)
void gemm_f16_kernel(const __half* __restrict__ A, const __half* __restrict__ Bt,
                     __half* __restrict__ C,
                     const float* __restrict__ rowscale,
                     const float* __restrict__ bias,
                     int M, int N, int K) {
    constexpr int BK = 32;
    constexpr int ROWH = 40;                 // smem row stride in halves
    __shared__ __half As[2][128 * ROWH];     // 20 KB
    __shared__ __half Bs[2][64 * ROWH];      // 10 KB

    const int tid  = threadIdx.x;
    const int warp = tid >> 5;
    const int lane = tid & 31;
    const int wm = warp & 3;
    const int wn = warp >> 2;
    const int quad = lane >> 3;
    const int qr   = lane & 7;

    const int brow0 = blockIdx.y * 128;
    const int bcol0 = blockIdx.x * 64;

    // staging coords: A 512 uint4 (2/thread), B 256 uint4 (1/thread)
    const int a_r0  = tid >> 2;              // rows 0..63 (l=0), 64..127 (l=1)
    const int a_c8  = tid & 3;
    const int b_n   = tid >> 2;              // 0..63
    const int b_c8  = tid & 3;

    // ldmatrix smem byte offsets (per thread, ks/buf added at use)
    unsigned as_base = (unsigned)__cvta_generic_to_shared(&As[0][0]);
    unsigned bs_base = (unsigned)__cvta_generic_to_shared(&Bs[0][0]);
    unsigned a_off[2], b_off[2];
#pragma unroll
    for (int mt = 0; mt < 2; mt++) {
        int row = wm * 32 + mt * 16 + qr + (quad & 1) * 8;
        a_off[mt] = (unsigned)((row * ROWH + (quad >> 1) * 8) * 2);
    }
#pragma unroll
    for (int ntp = 0; ntp < 2; ntp++) {
        int row = wn * 32 + ntp * 16 + (quad >> 1) * 8 + qr;
        b_off[ntp] = (unsigned)((row * ROWH + (quad & 1) * 8) * 2);
    }

    float acc[2][4][4];
#pragma unroll
    for (int mt = 0; mt < 2; mt++)
#pragma unroll
        for (int nt = 0; nt < 4; nt++)
#pragma unroll
            for (int f = 0; f < 4; f++) acc[mt][nt][f] = 0.f;

    uint4 ra[2], rb;
    auto load_tile = [&](int k0) {
#pragma unroll
        for (int l = 0; l < 2; l++) {
            int grow = brow0 + a_r0 + l * 64;
            ra[l] = make_uint4(0u, 0u, 0u, 0u);
            if (grow < M)
                ra[l] = *(const uint4*)(A + (size_t)grow * K + k0 + a_c8 * 8);
        }
        rb = *(const uint4*)(Bt + (size_t)(bcol0 + b_n) * K + k0 + b_c8 * 8);
    };

    load_tile(0);
    int buf = 0;

    for (int k0 = 0; k0 < K; k0 += BK) {
#pragma unroll
        for (int l = 0; l < 2; l++)
            *(uint4*)(&As[buf][(a_r0 + l * 64) * ROWH + a_c8 * 8]) = ra[l];
        *(uint4*)(&Bs[buf][b_n * ROWH + b_c8 * 8]) = rb;
        __syncthreads();

        if (k0 + BK < K) load_tile(k0 + BK);

        unsigned abuf = as_base + (unsigned)(buf * 128 * ROWH * 2);
        unsigned bbuf = bs_base + (unsigned)(buf * 64 * ROWH * 2);
#pragma unroll
        for (int ks = 0; ks < 2; ks++) {
            unsigned a[2][4], b[2][4];
#pragma unroll
            for (int mt = 0; mt < 2; mt++)
                ldsm_x4(a[mt][0], a[mt][1], a[mt][2], a[mt][3],
                        abuf + a_off[mt] + ks * 32);
#pragma unroll
            for (int ntp = 0; ntp < 2; ntp++)
                ldsm_x4(b[ntp][0], b[ntp][1], b[ntp][2], b[ntp][3],
                        bbuf + b_off[ntp] + ks * 32);
#pragma unroll
            for (int mt = 0; mt < 2; mt++)
#pragma unroll
                for (int nt = 0; nt < 4; nt++) {
                    unsigned b0 = b[nt >> 1][(nt & 1) * 2 + 0];
                    unsigned b1 = b[nt >> 1][(nt & 1) * 2 + 1];
                    mma_f16(acc[mt][nt][0], acc[mt][nt][1],
                            acc[mt][nt][2], acc[mt][nt][3],
                            a[mt][0], a[mt][1], a[mt][2], a[mt][3], b0, b1);
                }
        }
        buf ^= 1;
    }

    // ---- Epilogue (fp16 out)
    const int gid = lane >> 2;
    const int tig = lane & 3;
#pragma unroll
    for (int mt = 0; mt < 2; mt++) {
        int r0 = brow0 + wm * 32 + mt * 16 + gid;
        int r1 = r0 + 8;
        float rs0 = (r0 < M) ? __ldg(&rowscale[r0]) : 0.f;
        float rs1 = (r1 < M) ? __ldg(&rowscale[r1]) : 0.f;
#pragma unroll
        for (int nt = 0; nt < 4; nt++) {
            int c = bcol0 + wn * 32 + nt * 8 + 2 * tig;
            float2 bb = make_float2(0.f, 0.f);
            if (HAS_BIAS) bb = *(const float2*)(bias + c);
            float2 o0, o1;
            o0.x = acc[mt][nt][0] * rs0 + bb.x;
            o0.y = acc[mt][nt][1] * rs0 + bb.y;
            o1.x = acc[mt][nt][2] * rs1 + bb.x;
            o1.y = acc[mt][nt][3] * rs1 + bb.y;
            if (RELU) {
                o0.x = fmaxf(o0.x, 0.f); o0.y = fmaxf(o0.y, 0.f);
                o1.x = fmaxf(o1.x, 0.f); o1.y = fmaxf(o1.y, 0.f);
            }
            if (r0 < M) *(__half2*)(C + (size_t)r0 * N + c) = __floats2half2_rn(o0.x, o0.y);
            if (r1 < M) *(__half2*)(C + (size_t)r1 * N + c) = __floats2half2_rn(o1.x, o1.y);
        }
    }
}

// ----------------------------- launch ---------------------------------------
extern "C" void kernel_launch(void* const* d_in, const int* in_sizes, int n_in,
                              void* d_out, int out_size) {
    const float *features = nullptr, *W1 = nullptr, *b1 = nullptr,
                *W2 = nullptr, *b2 = nullptr;
    const int* ei = nullptr;
    for (int i = 0; i < n_in; i++) {
        switch (in_sizes[i]) {
            case NN * FIN:      features = (const float*)d_in[i]; break;
            case FIN * FHID:    W1 = (const float*)d_in[i]; break;
            case FHID:          b1 = (const float*)d_in[i]; break;
            case FHID * FOUT:   W2 = (const float*)d_in[i]; break;
            case FOUT:          b2 = (const float*)d_in[i]; break;
            case 2 * NE:        ei = (const int*)d_in[i]; break;
            default: break;
        }
    }
    float* out = (float*)d_out;

    float *onorm, *inorm;
    __half *agg1h, *x1h, *y_h, *feat_h, *w1t, *w2t;
    int *deg, *off, *cursor, *csr_src, *incl, *bsum, *bpre;
    cudaGetSymbolAddress((void**)&agg1h,   g_agg1h);
    cudaGetSymbolAddress((void**)&x1h,     g_x1h);
    cudaGetSymbolAddress((void**)&y_h,     g_y_h);
    cudaGetSymbolAddress((void**)&feat_h,  g_feat_h);
    cudaGetSymbolAddress((void**)&w1t,     g_w1t);
    cudaGetSymbolAddress((void**)&w2t,     g_w2t);
    cudaGetSymbolAddress((void**)&onorm,   g_out_norm);
    cudaGetSymbolAddress((void**)&inorm,   g_in_norm);
    cudaGetSymbolAddress((void**)&deg,     g_deg);
    cudaGetSymbolAddress((void**)&off,     g_off);
    cudaGetSymbolAddress((void**)&cursor,  g_cursor);
    cudaGetSymbolAddress((void**)&csr_src, g_csr_src);
    cudaGetSymbolAddress((void**)&incl,    g_incl);
    cudaGetSymbolAddress((void**)&bsum,    g_bsum);
    cudaGetSymbolAddress((void**)&bpre,    g_bpre);

    const int T = 256;

    cudaMemsetAsync(deg, 0, 2 * NN * sizeof(int));
    // [k1] weight transpose+convert (independent)
    wconv_kernel<<<(FOUT * FHID + T - 1) / T, T>>>(W1, W2, w1t, w2t);
    // [k2] degrees
    degree_kernel<<<(NE + T - 1) / T, T>>>(ei, deg);
    // [k3..k5] coalesced 3-phase scan + norms
    scan1_kernel<<<NB, 256>>>(deg, incl, bsum);
    scan2_kernel<<<1, 256>>>(bsum, bpre);
    scan3_kernel<<<NB, 256>>>(deg, incl, bpre, off, cursor, onorm, inorm);
    // [k6] counting-sort scatter + scaled fp16 features
    scatter_f2h_kernel<<<(NE + T - 1) / T, T>>>(ei, cursor, csr_src,
                                                features, onorm, feat_h);
    // [k7] agg1_h = fp16(gather(feat_h))
    {
        long long threads = (long long)NN * 32;
        agg1_gather_kernel<<<(unsigned)((threads + T - 1) / T), T>>>(
            off, csr_src, feat_h, agg1h);
    }
    // [k8] x1_h = fp16(relu( inorm[row] * (agg1 @ W1) + b1 ))
    {
        dim3 grid(FHID / 64, (NN + 127) / 128);
        gemm_f16_kernel<true, true><<<grid, 256>>>(agg1h, w1t, x1h, inorm, b1,
                                                   NN, FHID, FIN);
    }
    // [k9] y_h = fp16( onorm[row] * (x1 @ W2) )
    {
        dim3 grid(FOUT / 64, (NN + 127) / 128);
        gemm_f16_kernel<false, false><<<grid, 256>>>(x1h, w2t, y_h, onorm, nullptr,
                                                     NN, FOUT, FHID);
    }
    // [k10] out = inorm[row] * gather(y_h) + b2
    {
        long long threads = (long long)NN * 32;
        agg2_gather_kernel<<<(unsigned)((threads + T - 1) / T), T>>>(
            off, csr_src, y_h, inorm, b2, out);
    }
}

// round 8
// speedup vs baseline: 2.3189x; 1.1539x over previous
#include <cuda_runtime.h>
#include <cuda_fp16.h>
#include <cstdint>

#define NN   50000
#define NE   800000
#define FIN  128
#define FHID 384
#define FOUT 256
#define NB   196          // ceil(NN/256) scan blocks

// ----------------------------- scratch --------------------------------------
__device__ __half g_agg1h[NN * FIN];             // 12.8 MB
__device__ __half g_x1h[(size_t)NN * FHID];      // 38.4 MB
__device__ __half g_y_h[(size_t)NN * FOUT];      // 25.6 MB
__device__ __half g_feat_h[NN * FIN];            // 12.8 MB (features * out_norm)
__device__ __half g_w1t[FHID * FIN];             // W1^T fp16 [384][128]
__device__ __half g_w2t[FOUT * FHID];            // W2^T fp16 [256][384]
__device__ int    g_deg[2 * NN];
__device__ float  g_out_norm[NN];
__device__ float  g_in_norm[NN];
__device__ int    g_off[NN + 1];
__device__ int    g_cursor[NN];
__device__ int    g_csr_src[NE];
__device__ int    g_incl[NN];
__device__ int    g_bsum[256];
__device__ int    g_bpre[256];

// ----------------------------- helpers --------------------------------------
__device__ __forceinline__ void ldsm_x4(unsigned& r0, unsigned& r1,
                                        unsigned& r2, unsigned& r3, unsigned addr) {
    asm volatile("ldmatrix.sync.aligned.m8n8.x4.shared.b16 {%0,%1,%2,%3}, [%4];"
                 : "=r"(r0), "=r"(r1), "=r"(r2), "=r"(r3) : "r"(addr));
}

__device__ __forceinline__ void mma_f16(float& c0, float& c1, float& c2, float& c3,
                                        unsigned a0, unsigned a1, unsigned a2, unsigned a3,
                                        unsigned b0, unsigned b1) {
    asm volatile("mma.sync.aligned.m16n8k16.row.col.f32.f16.f16.f32 "
                 "{%0,%1,%2,%3}, {%4,%5,%6,%7}, {%8,%9}, {%0,%1,%2,%3};"
                 : "+f"(c0), "+f"(c1), "+f"(c2), "+f"(c3)
                 : "r"(a0), "r"(a1), "r"(a2), "r"(a3), "r"(b0), "r"(b1));
}

__device__ __forceinline__ void cp16(unsigned dst, const void* src, int src_sz) {
    asm volatile("cp.async.cg.shared.global [%0], [%1], 16, %2;"
                 :: "r"(dst), "l"(src), "r"(src_sz));
}
__device__ __forceinline__ void cp_commit() {
    asm volatile("cp.async.commit_group;");
}
template<int N_>
__device__ __forceinline__ void cp_wait() {
    asm volatile("cp.async.wait_group %0;" :: "n"(N_));
}

__device__ __forceinline__ __half2 bits2h(unsigned u) {
    return *reinterpret_cast<__half2*>(&u);
}

// ----------------------------- prelude kernels -------------------------------
// Tiled transpose + fp16 convert: Wt[n][k] = fp16(W[k][n]). R = rows(K), C = cols(N).
__global__ void wtrans_kernel(const float* __restrict__ W, __half* __restrict__ Wt,
                              int R, int C) {
    __shared__ float tile[32][33];
    int bx = blockIdx.x * 32;   // col base (n)
    int by = blockIdx.y * 32;   // row base (k)
    int x = bx + threadIdx.x;
#pragma unroll
    for (int i = 0; i < 32; i += 8) {
        int y = by + threadIdx.y + i;
        if (y < R && x < C) tile[threadIdx.y + i][threadIdx.x] = W[(size_t)y * C + x];
    }
    __syncthreads();
    int k = by + threadIdx.x;
#pragma unroll
    for (int i = 0; i < 32; i += 8) {
        int n = bx + threadIdx.y + i;
        if (n < C && k < R)
            Wt[(size_t)n * R + k] = __float2half(tile[threadIdx.x][threadIdx.y + i]);
    }
}

__global__ void degree_kernel(const int* __restrict__ ei, int* __restrict__ deg) {
    int e = blockIdx.x * blockDim.x + threadIdx.x;
    if (e < NE) {
        atomicAdd(&deg[ei[e]], 1);
        atomicAdd(&deg[NN + ei[NE + e]], 1);
    }
}

__global__ void scan1_kernel(const int* __restrict__ deg,
                             int* __restrict__ incl, int* __restrict__ bsum) {
    __shared__ int sh[256];
    int t = threadIdx.x;
    int i = blockIdx.x * 256 + t;
    int v = (i < NN) ? deg[NN + i] : 0;
    sh[t] = v;
    __syncthreads();
#pragma unroll
    for (int d = 1; d < 256; d <<= 1) {
        int x = (t >= d) ? sh[t - d] : 0;
        __syncthreads();
        if (t >= d) sh[t] += x;
        __syncthreads();
    }
    if (i < NN) incl[i] = sh[t];
    if (t == 255) bsum[blockIdx.x] = sh[255];
}

__global__ void scan2_kernel(const int* __restrict__ bsum, int* __restrict__ bpre) {
    __shared__ int sh[256];
    int t = threadIdx.x;
    int v = (t < NB) ? bsum[t] : 0;
    sh[t] = v;
    __syncthreads();
#pragma unroll
    for (int d = 1; d < 256; d <<= 1) {
        int x = (t >= d) ? sh[t - d] : 0;
        __syncthreads();
        if (t >= d) sh[t] += x;
        __syncthreads();
    }
    bpre[t] = sh[t] - v;
}

__global__ void scan3_kernel(const int* __restrict__ deg,
                             const int* __restrict__ incl, const int* __restrict__ bpre,
                             int* __restrict__ off, int* __restrict__ cursor,
                             float* __restrict__ onorm, float* __restrict__ inorm) {
    int i = blockIdx.x * 256 + threadIdx.x;
    if (i < NN) {
        int din = deg[NN + i];
        int excl = bpre[blockIdx.x] + incl[i] - din;
        off[i] = excl;
        cursor[i] = excl;
        onorm[i] = rsqrtf((float)max(deg[i], 1));
        inorm[i] = rsqrtf((float)max(din, 1));
    }
    if (i == 0) off[NN] = NE;
}

__global__ void scatter_f2h_kernel(const int* __restrict__ ei,
                                   int* __restrict__ cursor,
                                   int* __restrict__ csr_src,
                                   const float* __restrict__ feat,
                                   const float* __restrict__ onorm,
                                   __half* __restrict__ feat_h) {
    int e = blockIdx.x * blockDim.x + threadIdx.x;
    if (e < NE) {
        int src = ei[e];
        int dst = ei[NE + e];
        int pos = atomicAdd(&cursor[dst], 1);
        csr_src[pos] = src;
    }
    const int n4 = NN * (FIN / 4);
    int total = blockDim.x * gridDim.x;
    for (int i = e; i < n4; i += total) {
        int row = i >> 5;
        float sc = __ldg(&onorm[row]);
        float4 v = ((const float4*)feat)[i];
        __half2 h0 = __floats2half2_rn(v.x * sc, v.y * sc);
        __half2 h1 = __floats2half2_rn(v.z * sc, v.w * sc);
        ((uint2*)feat_h)[i] = make_uint2(*(unsigned*)&h0, *(unsigned*)&h1);
    }
}

// ----------------------------- gathers ---------------------------------------
__global__ void agg1_gather_kernel(const int* __restrict__ off,
                                   const int* __restrict__ csr_src,
                                   const __half* __restrict__ feat,
                                   __half* __restrict__ aggh) {
    int n = (blockIdx.x * blockDim.x + threadIdx.x) >> 5;
    if (n >= NN) return;
    int lane = threadIdx.x & 31;
    int beg = off[n], end = off[n + 1];
    float4 acc = make_float4(0.f, 0.f, 0.f, 0.f);
    for (int j = beg; j < end; j += 32) {
        int m = min(32, end - j);
        int s = (lane < m) ? __ldg(&csr_src[j + lane]) : 0;
        int k = 0;
        for (; k + 4 <= m; k += 4) {
            int s0 = __shfl_sync(0xffffffffu, s, k + 0);
            int s1 = __shfl_sync(0xffffffffu, s, k + 1);
            int s2 = __shfl_sync(0xffffffffu, s, k + 2);
            int s3 = __shfl_sync(0xffffffffu, s, k + 3);
            uint2 u0 = __ldg((const uint2*)(feat + (size_t)s0 * FIN + lane * 4));
            uint2 u1 = __ldg((const uint2*)(feat + (size_t)s1 * FIN + lane * 4));
            uint2 u2 = __ldg((const uint2*)(feat + (size_t)s2 * FIN + lane * 4));
            uint2 u3 = __ldg((const uint2*)(feat + (size_t)s3 * FIN + lane * 4));
            float2 a, b;
            a = __half22float2(bits2h(u0.x)); b = __half22float2(bits2h(u0.y));
            acc.x += a.x; acc.y += a.y; acc.z += b.x; acc.w += b.y;
            a = __half22float2(bits2h(u1.x)); b = __half22float2(bits2h(u1.y));
            acc.x += a.x; acc.y += a.y; acc.z += b.x; acc.w += b.y;
            a = __half22float2(bits2h(u2.x)); b = __half22float2(bits2h(u2.y));
            acc.x += a.x; acc.y += a.y; acc.z += b.x; acc.w += b.y;
            a = __half22float2(bits2h(u3.x)); b = __half22float2(bits2h(u3.y));
            acc.x += a.x; acc.y += a.y; acc.z += b.x; acc.w += b.y;
        }
        for (; k < m; k++) {
            int ss = __shfl_sync(0xffffffffu, s, k);
            uint2 u = __ldg((const uint2*)(feat + (size_t)ss * FIN + lane * 4));
            float2 a = __half22float2(bits2h(u.x));
            float2 b = __half22float2(bits2h(u.y));
            acc.x += a.x; acc.y += a.y; acc.z += b.x; acc.w += b.y;
        }
    }
    __half2 h0 = __floats2half2_rn(acc.x, acc.y);
    __half2 h1 = __floats2half2_rn(acc.z, acc.w);
    ((uint2*)(aggh + (size_t)n * FIN))[lane] = make_uint2(*(unsigned*)&h0, *(unsigned*)&h1);
}

__device__ __forceinline__ void acc8(float* acc, uint4 u) {
    float2 f;
    f = __half22float2(bits2h(u.x)); acc[0] += f.x; acc[1] += f.y;
    f = __half22float2(bits2h(u.y)); acc[2] += f.x; acc[3] += f.y;
    f = __half22float2(bits2h(u.z)); acc[4] += f.x; acc[5] += f.y;
    f = __half22float2(bits2h(u.w)); acc[6] += f.x; acc[7] += f.y;
}

__global__ void agg2_gather_kernel(const int* __restrict__ off,
                                   const int* __restrict__ csr_src,
                                   const __half* __restrict__ y,
                                   const float* __restrict__ inorm,
                                   const float* __restrict__ b2,
                                   float* __restrict__ out) {
    int n = (blockIdx.x * blockDim.x + threadIdx.x) >> 5;
    if (n >= NN) return;
    int lane = threadIdx.x & 31;
    int beg = off[n], end = off[n + 1];
    float acc[8] = {0.f, 0.f, 0.f, 0.f, 0.f, 0.f, 0.f, 0.f};
    for (int j = beg; j < end; j += 32) {
        int m = min(32, end - j);
        int s = (lane < m) ? __ldg(&csr_src[j + lane]) : 0;
        int k = 0;
        for (; k + 4 <= m; k += 4) {
            int s0 = __shfl_sync(0xffffffffu, s, k + 0);
            int s1 = __shfl_sync(0xffffffffu, s, k + 1);
            int s2 = __shfl_sync(0xffffffffu, s, k + 2);
            int s3 = __shfl_sync(0xffffffffu, s, k + 3);
            uint4 u0 = __ldg((const uint4*)(y + (size_t)s0 * FOUT + lane * 8));
            uint4 u1 = __ldg((const uint4*)(y + (size_t)s1 * FOUT + lane * 8));
            uint4 u2 = __ldg((const uint4*)(y + (size_t)s2 * FOUT + lane * 8));
            uint4 u3 = __ldg((const uint4*)(y + (size_t)s3 * FOUT + lane * 8));
            acc8(acc, u0); acc8(acc, u1); acc8(acc, u2); acc8(acc, u3);
        }
        for (; k < m; k++) {
            int ss = __shfl_sync(0xffffffffu, s, k);
            uint4 u = __ldg((const uint4*)(y + (size_t)ss * FOUT + lane * 8));
            acc8(acc, u);
        }
    }
    float sc = __ldg(&inorm[n]);
    float4 bb0 = *(const float4*)(b2 + lane * 8);
    float4 bb1 = *(const float4*)(b2 + lane * 8 + 4);
    float4 o0, o1;
    o0.x = acc[0] * sc + bb0.x; o0.y = acc[1] * sc + bb0.y;
    o0.z = acc[2] * sc + bb0.z; o0.w = acc[3] * sc + bb0.w;
    o1.x = acc[4] * sc + bb1.x; o1.y = acc[5] * sc + bb1.y;
    o1.z = acc[6] * sc + bb1.z; o1.w = acc[7] * sc + bb1.w;
    float* orow = out + (size_t)n * FOUT + lane * 8;
    *(float4*)orow = o0;
    *(float4*)(orow + 4) = o1;
}

// ----------------------------- fp16 tensor GEMM (cp.async, BK=64) ------------
// C[M,N](fp16) = epi( (A[M,K] @ Bt[N,K]^T) * rowscale[row] (+bias) (relu) )
// BM=128, BN=64, BK=64; 8 warps (4M x 2N). cp.async double-buffered staging.
// Dynamic smem: As 2x128x72, Bs 2x64x72 halves = 54KB.
#define ROWH 72
#define GEMM_SMEM ((2 * 128 * ROWH + 2 * 64 * ROWH) * 2)

template<bool RELU, bool HAS_BIAS>
__global__ __launch_bounds__(256)
void gemm_f16_kernel(const __half* __restrict__ A, const __half* __restrict__ Bt,
                     __half* __restrict__ C,
                     const float* __restrict__ rowscale,
                     const float* __restrict__ bias,
                     int M, int N, int K) {
    constexpr int BK = 64;
    extern __shared__ __align__(16) __half dynsmem[];
    __half* As = dynsmem;                       // [2][128*ROWH]
    __half* Bs = dynsmem + 2 * 128 * ROWH;      // [2][64*ROWH]

    const int tid  = threadIdx.x;
    const int warp = tid >> 5;
    const int lane = tid & 31;
    const int wm = warp & 3;
    const int wn = warp >> 2;
    const int quad = lane >> 3;
    const int qr   = lane & 7;

    const int brow0 = blockIdx.y * 128;
    const int bcol0 = blockIdx.x * 64;

    // staging coords: 8 x 16B per row; A 128 rows (4 iters), B 64 rows (2 iters)
    const int st_c8 = tid & 7;
    const int st_r  = tid >> 3;    // 0..31

    unsigned as_base = (unsigned)__cvta_generic_to_shared(As);
    unsigned bs_base = (unsigned)__cvta_generic_to_shared(Bs);

    // ldmatrix per-thread offsets (bytes, within one buffer)
    unsigned a_off[2], b_off[2];
#pragma unroll
    for (int mt = 0; mt < 2; mt++) {
        int row = wm * 32 + mt * 16 + qr + (quad & 1) * 8;
        a_off[mt] = (unsigned)((row * ROWH + (quad >> 1) * 8) * 2);
    }
#pragma unroll
    for (int ntp = 0; ntp < 2; ntp++) {
        int row = wn * 32 + ntp * 16 + (quad >> 1) * 8 + qr;
        b_off[ntp] = (unsigned)((row * ROWH + (quad & 1) * 8) * 2);
    }

    float acc[2][4][4];
#pragma unroll
    for (int mt = 0; mt < 2; mt++)
#pragma unroll
        for (int nt = 0; nt < 4; nt++)
#pragma unroll
            for (int f = 0; f < 4; f++) acc[mt][nt][f] = 0.f;

    auto stage = [&](int k0, int buf) {
#pragma unroll
        for (int l = 0; l < 4; l++) {
            int row = st_r + l * 32;
            int grow = brow0 + row;
            unsigned dst = as_base + (unsigned)((buf * 128 * ROWH + row * ROWH + st_c8 * 8) * 2);
            const __half* src = A + (size_t)grow * K + k0 + st_c8 * 8;
            cp16(dst, src, (grow < M) ? 16 : 0);
        }
#pragma unroll
        for (int l = 0; l < 2; l++) {
            int row = st_r + l * 32;
            unsigned dst = bs_base + (unsigned)((buf * 64 * ROWH + row * ROWH + st_c8 * 8) * 2);
            const __half* src = Bt + (size_t)(bcol0 + row) * K + k0 + st_c8 * 8;
            cp16(dst, src, 16);
        }
        cp_commit();
    };

    stage(0, 0);
    int buf = 0;
    const int KT = K / BK;

    for (int kt = 0; kt < KT; kt++) {
        if (kt + 1 < KT) {
            stage((kt + 1) * BK, buf ^ 1);
            cp_wait<1>();
        } else {
            cp_wait<0>();
        }
        __syncthreads();

        unsigned abuf = as_base + (unsigned)(buf * 128 * ROWH * 2);
        unsigned bbuf = bs_base + (unsigned)(buf * 64 * ROWH * 2);
#pragma unroll
        for (int ks = 0; ks < 4; ks++) {
            unsigned a[2][4], b[2][4];
#pragma unroll
            for (int mt = 0; mt < 2; mt++)
                ldsm_x4(a[mt][0], a[mt][1], a[mt][2], a[mt][3],
                        abuf + a_off[mt] + ks * 32);
#pragma unroll
            for (int ntp = 0; ntp < 2; ntp++)
                ldsm_x4(b[ntp][0], b[ntp][1], b[ntp][2], b[ntp][3],
                        bbuf + b_off[ntp] + ks * 32);
#pragma unroll
            for (int mt = 0; mt < 2; mt++)
#pragma unroll
                for (int nt = 0; nt < 4; nt++) {
                    unsigned b0 = b[nt >> 1][(nt & 1) * 2 + 0];
                    unsigned b1 = b[nt >> 1][(nt & 1) * 2 + 1];
                    mma_f16(acc[mt][nt][0], acc[mt][nt][1],
                            acc[mt][nt][2], acc[mt][nt][3],
                            a[mt][0], a[mt][1], a[mt][2], a[mt][3], b0, b1);
                }
        }
        __syncthreads();   // all reads of buf done before it is re-staged
        buf ^= 1;
    }

    // ---- Epilogue (fp16 out)
    const int gid = lane >> 2;
    const int tig = lane & 3;
#pragma unroll
    for (int mt = 0; mt < 2; mt++) {
        int r0 = brow0 + wm * 32 + mt * 16 + gid;
        int r1 = r0 + 8;
        float rs0 = (r0 < M) ? __ldg(&rowscale[r0]) : 0.f;
        float rs1 = (r1 < M) ? __ldg(&rowscale[r1]) : 0.f;
#pragma unroll
        for (int nt = 0; nt < 4; nt++) {
            int c = bcol0 + wn * 32 + nt * 8 + 2 * tig;
            float2 bb = make_float2(0.f, 0.f);
            if (HAS_BIAS) bb = *(const float2*)(bias + c);
            float2 o0, o1;
            o0.x = acc[mt][nt][0] * rs0 + bb.x;
            o0.y = acc[mt][nt][1] * rs0 + bb.y;
            o1.x = acc[mt][nt][2] * rs1 + bb.x;
            o1.y = acc[mt][nt][3] * rs1 + bb.y;
            if (RELU) {
                o0.x = fmaxf(o0.x, 0.f); o0.y = fmaxf(o0.y, 0.f);
                o1.x = fmaxf(o1.x, 0.f); o1.y = fmaxf(o1.y, 0.f);
            }
            if (r0 < M) *(__half2*)(C + (size_t)r0 * N + c) = __floats2half2_rn(o0.x, o0.y);
            if (r1 < M) *(__half2*)(C + (size_t)r1 * N + c) = __floats2half2_rn(o1.x, o1.y);
        }
    }
}

// ----------------------------- launch ---------------------------------------
extern "C" void kernel_launch(void* const* d_in, const int* in_sizes, int n_in,
                              void* d_out, int out_size) {
    const float *features = nullptr, *W1 = nullptr, *b1 = nullptr,
                *W2 = nullptr, *b2 = nullptr;
    const int* ei = nullptr;
    for (int i = 0; i < n_in; i++) {
        switch (in_sizes[i]) {
            case NN * FIN:      features = (const float*)d_in[i]; break;
            case FIN * FHID:    W1 = (const float*)d_in[i]; break;
            case FHID:          b1 = (const float*)d_in[i]; break;
            case FHID * FOUT:   W2 = (const float*)d_in[i]; break;
            case FOUT:          b2 = (const float*)d_in[i]; break;
            case 2 * NE:        ei = (const int*)d_in[i]; break;
            default: break;
        }
    }
    float* out = (float*)d_out;

    float *onorm, *inorm;
    __half *agg1h, *x1h, *y_h, *feat_h, *w1t, *w2t;
    int *deg, *off, *cursor, *csr_src, *incl, *bsum, *bpre;
    cudaGetSymbolAddress((void**)&agg1h,   g_agg1h);
    cudaGetSymbolAddress((void**)&x1h,     g_x1h);
    cudaGetSymbolAddress((void**)&y_h,     g_y_h);
    cudaGetSymbolAddress((void**)&feat_h,  g_feat_h);
    cudaGetSymbolAddress((void**)&w1t,     g_w1t);
    cudaGetSymbolAddress((void**)&w2t,     g_w2t);
    cudaGetSymbolAddress((void**)&onorm,   g_out_norm);
    cudaGetSymbolAddress((void**)&inorm,   g_in_norm);
    cudaGetSymbolAddress((void**)&deg,     g_deg);
    cudaGetSymbolAddress((void**)&off,     g_off);
    cudaGetSymbolAddress((void**)&cursor,  g_cursor);
    cudaGetSymbolAddress((void**)&csr_src, g_csr_src);
    cudaGetSymbolAddress((void**)&incl,    g_incl);
    cudaGetSymbolAddress((void**)&bsum,    g_bsum);
    cudaGetSymbolAddress((void**)&bpre,    g_bpre);

    cudaFuncSetAttribute(gemm_f16_kernel<true, true>,
                         cudaFuncAttributeMaxDynamicSharedMemorySize, GEMM_SMEM);
    cudaFuncSetAttribute(gemm_f16_kernel<false, false>,
                         cudaFuncAttributeMaxDynamicSharedMemorySize, GEMM_SMEM);

    const int T = 256;

    cudaMemsetAsync(deg, 0, 2 * NN * sizeof(int));
    // weight transposes (independent of graph chain)
    {
        dim3 b(32, 8);
        wtrans_kernel<<<dim3(FHID / 32, FIN / 32), b>>>(W1, w1t, FIN, FHID);
        wtrans_kernel<<<dim3(FOUT / 32, FHID / 32), b>>>(W2, w2t, FHID, FOUT);
    }
    degree_kernel<<<(NE + T - 1) / T, T>>>(ei, deg);
    scan1_kernel<<<NB, 256>>>(deg, incl, bsum);
    scan2_kernel<<<1, 256>>>(bsum, bpre);
    scan3_kernel<<<NB, 256>>>(deg, incl, bpre, off, cursor, onorm, inorm);
    scatter_f2h_kernel<<<(NE + T - 1) / T, T>>>(ei, cursor, csr_src,
                                                features, onorm, feat_h);
    {
        long long threads = (long long)NN * 32;
        agg1_gather_kernel<<<(unsigned)((threads + T - 1) / T), T>>>(
            off, csr_src, feat_h, agg1h);
    }
    {
        dim3 grid(FHID / 64, (NN + 127) / 128);
        gemm_f16_kernel<true, true><<<grid, 256, GEMM_SMEM>>>(
            agg1h, w1t, x1h, inorm, b1, NN, FHID, FIN);
    }
    {
        dim3 grid(FOUT / 64, (NN + 127) / 128);
        gemm_f16_kernel<false, false><<<grid, 256, GEMM_SMEM>>>(
            x1h, w2t, y_h, onorm, nullptr, NN, FOUT, FHID);
    }
    {
        long long threads = (long long)NN * 32;
        agg2_gather_kernel<<<(unsigned)((threads + T - 1) / T), T>>>(
            off, csr_src, y_h, inorm, b2, out);
    }
}

// round 11
// speedup vs baseline: 2.4210x; 1.0440x over previous
#include <cuda_runtime.h>
#include <cuda_fp16.h>
#include <cstdint>

#define NN   50000
#define NE   800000
#define FIN  128
#define FHID 384
#define FOUT 256
#define NB   196          // ceil(NN/256) scan blocks

// ----------------------------- scratch --------------------------------------
__device__ __half g_agg1h[NN * FIN];             // 12.8 MB
__device__ __half g_x1h[(size_t)NN * FHID];      // 38.4 MB
__device__ __half g_y_h[(size_t)NN * FOUT];      // 25.6 MB
__device__ __half g_feat_h[NN * FIN];            // 12.8 MB (features * out_norm)
__device__ __half g_w1t[FHID * FIN];             // W1^T fp16 [384][128]
__device__ __half g_w2t[FOUT * FHID];            // W2^T fp16 [256][384]
__device__ int    g_deg[2 * NN];
__device__ float  g_out_norm[NN];
__device__ float  g_in_norm[NN];
__device__ int    g_off[NN + 1];
__device__ int    g_cursor[NN];
__device__ int    g_csr_src[NE];
__device__ int    g_incl[NN];
__device__ int    g_bsum[256];

// ----------------------------- helpers --------------------------------------
__device__ __forceinline__ void ldsm_x4(unsigned& r0, unsigned& r1,
                                        unsigned& r2, unsigned& r3, unsigned addr) {
    asm volatile("ldmatrix.sync.aligned.m8n8.x4.shared.b16 {%0,%1,%2,%3}, [%4];"
                 : "=r"(r0), "=r"(r1), "=r"(r2), "=r"(r3) : "r"(addr));
}

__device__ __forceinline__ void mma_f16(float& c0, float& c1, float& c2, float& c3,
                                        unsigned a0, unsigned a1, unsigned a2, unsigned a3,
                                        unsigned b0, unsigned b1) {
    asm volatile("mma.sync.aligned.m16n8k16.row.col.f32.f16.f16.f32 "
                 "{%0,%1,%2,%3}, {%4,%5,%6,%7}, {%8,%9}, {%0,%1,%2,%3};"
                 : "+f"(c0), "+f"(c1), "+f"(c2), "+f"(c3)
                 : "r"(a0), "r"(a1), "r"(a2), "r"(a3), "r"(b0), "r"(b1));
}

__device__ __forceinline__ void cp16(unsigned dst, const void* src, int src_sz) {
    asm volatile("cp.async.cg.shared.global [%0], [%1], 16, %2;"
                 :: "r"(dst), "l"(src), "r"(src_sz));
}
__device__ __forceinline__ void cp_commit() { asm volatile("cp.async.commit_group;"); }
template<int N_>
__device__ __forceinline__ void cp_wait() {
    asm volatile("cp.async.wait_group %0;" :: "n"(N_));
}
__device__ __forceinline__ __half2 bits2h(unsigned u) {
    return *reinterpret_cast<__half2*>(&u);
}

// ----------------------------- prelude kernels -------------------------------
__global__ void wtrans_kernel(const float* __restrict__ W, __half* __restrict__ Wt,
                              int R, int C) {
    __shared__ float tile[32][33];
    int bx = blockIdx.x * 32, by = blockIdx.y * 32;
    int x = bx + threadIdx.x;
#pragma unroll
    for (int i = 0; i < 32; i += 8) {
        int y = by + threadIdx.y + i;
        if (y < R && x < C) tile[threadIdx.y + i][threadIdx.x] = W[(size_t)y * C + x];
    }
    __syncthreads();
    int k = by + threadIdx.x;
#pragma unroll
    for (int i = 0; i < 32; i += 8) {
        int n = bx + threadIdx.y + i;
        if (n < C && k < R)
            Wt[(size_t)n * R + k] = __float2half(tile[threadIdx.x][threadIdx.y + i]);
    }
}

__global__ void degree_kernel(const int* __restrict__ ei, int* __restrict__ deg) {
    int e = blockIdx.x * blockDim.x + threadIdx.x;
    if (e < NE) {
        atomicAdd(&deg[ei[e]], 1);
        atomicAdd(&deg[NN + ei[NE + e]], 1);
    }
}

__global__ void scan1_kernel(const int* __restrict__ deg,
                             int* __restrict__ incl, int* __restrict__ bsum) {
    __shared__ int sh[256];
    int t = threadIdx.x;
    int i = blockIdx.x * 256 + t;
    int v = (i < NN) ? deg[NN + i] : 0;
    sh[t] = v;
    __syncthreads();
#pragma unroll
    for (int d = 1; d < 256; d <<= 1) {
        int x = (t >= d) ? sh[t - d] : 0;
        __syncthreads();
        if (t >= d) sh[t] += x;
        __syncthreads();
    }
    if (i < NN) incl[i] = sh[t];
    if (t == 255) bsum[blockIdx.x] = sh[255];
}

// scan3 with inlined block-prefix: each block sums bsum[0..bid)
__global__ void scan3_kernel(const int* __restrict__ deg,
                             const int* __restrict__ incl, const int* __restrict__ bsum,
                             int* __restrict__ off, int* __restrict__ cursor,
                             float* __restrict__ onorm, float* __restrict__ inorm) {
    __shared__ int sh[256];
    int t = threadIdx.x;
    sh[t] = (t < blockIdx.x && t < NB) ? bsum[t] : 0;
    __syncthreads();
#pragma unroll
    for (int d = 128; d > 0; d >>= 1) {
        if (t < d) sh[t] += sh[t + d];
        __syncthreads();
    }
    int bpre = sh[0];
    int i = blockIdx.x * 256 + t;
    if (i < NN) {
        int din = deg[NN + i];
        int excl = bpre + incl[i] - din;
        off[i] = excl;
        cursor[i] = excl;
        onorm[i] = rsqrtf((float)max(deg[i], 1));
        inorm[i] = rsqrtf((float)max(din, 1));
    }
    if (i == 0) off[NN] = NE;
}

__global__ void scatter_f2h_kernel(const int* __restrict__ ei,
                                   int* __restrict__ cursor,
                                   int* __restrict__ csr_src,
                                   const float* __restrict__ feat,
                                   const float* __restrict__ onorm,
                                   __half* __restrict__ feat_h) {
    int e = blockIdx.x * blockDim.x + threadIdx.x;
    if (e < NE) {
        int src = ei[e];
        int dst = ei[NE + e];
        int pos = atomicAdd(&cursor[dst], 1);
        csr_src[pos] = src;
    }
    const int n4 = NN * (FIN / 4);
    int total = blockDim.x * gridDim.x;
    for (int i = e; i < n4; i += total) {
        int row = i >> 5;
        float sc = __ldg(&onorm[row]);
        float4 v = ((const float4*)feat)[i];
        __half2 h0 = __floats2half2_rn(v.x * sc, v.y * sc);
        __half2 h1 = __floats2half2_rn(v.z * sc, v.w * sc);
        ((uint2*)feat_h)[i] = make_uint2(*(unsigned*)&h0, *(unsigned*)&h1);
    }
}

// ----------------------------- gathers ---------------------------------------
__global__ void agg1_gather_kernel(const int* __restrict__ off,
                                   const int* __restrict__ csr_src,
                                   const __half* __restrict__ feat,
                                   __half* __restrict__ aggh) {
    int n = (blockIdx.x * blockDim.x + threadIdx.x) >> 5;
    if (n >= NN) return;
    int lane = threadIdx.x & 31;
    int beg = off[n], end = off[n + 1];
    float4 acc = make_float4(0.f, 0.f, 0.f, 0.f);
    for (int j = beg; j < end; j += 32) {
        int m = min(32, end - j);
        int s = (lane < m) ? __ldg(&csr_src[j + lane]) : 0;
        int k = 0;
        for (; k + 4 <= m; k += 4) {
            int s0 = __shfl_sync(0xffffffffu, s, k + 0);
            int s1 = __shfl_sync(0xffffffffu, s, k + 1);
            int s2 = __shfl_sync(0xffffffffu, s, k + 2);
            int s3 = __shfl_sync(0xffffffffu, s, k + 3);
            uint2 u0 = __ldg((const uint2*)(feat + (size_t)s0 * FIN + lane * 4));
            uint2 u1 = __ldg((const uint2*)(feat + (size_t)s1 * FIN + lane * 4));
            uint2 u2 = __ldg((const uint2*)(feat + (size_t)s2 * FIN + lane * 4));
            uint2 u3 = __ldg((const uint2*)(feat + (size_t)s3 * FIN + lane * 4));
            float2 a, b;
            a = __half22float2(bits2h(u0.x)); b = __half22float2(bits2h(u0.y));
            acc.x += a.x; acc.y += a.y; acc.z += b.x; acc.w += b.y;
            a = __half22float2(bits2h(u1.x)); b = __half22float2(bits2h(u1.y));
            acc.x += a.x; acc.y += a.y; acc.z += b.x; acc.w += b.y;
            a = __half22float2(bits2h(u2.x)); b = __half22float2(bits2h(u2.y));
            acc.x += a.x; acc.y += a.y; acc.z += b.x; acc.w += b.y;
            a = __half22float2(bits2h(u3.x)); b = __half22float2(bits2h(u3.y));
            acc.x += a.x; acc.y += a.y; acc.z += b.x; acc.w += b.y;
        }
        for (; k < m; k++) {
            int ss = __shfl_sync(0xffffffffu, s, k);
            uint2 u = __ldg((const uint2*)(feat + (size_t)ss * FIN + lane * 4));
            float2 a = __half22float2(bits2h(u.x));
            float2 b = __half22float2(bits2h(u.y));
            acc.x += a.x; acc.y += a.y; acc.z += b.x; acc.w += b.y;
        }
    }
    __half2 h0 = __floats2half2_rn(acc.x, acc.y);
    __half2 h1 = __floats2half2_rn(acc.z, acc.w);
    ((uint2*)(aggh + (size_t)n * FIN))[lane] = make_uint2(*(unsigned*)&h0, *(unsigned*)&h1);
}

__device__ __forceinline__ void acc4(float* acc, uint2 u) {
    float2 f;
    f = __half22float2(bits2h(u.x)); acc[0] += f.x; acc[1] += f.y;
    f = __half22float2(bits2h(u.y)); acc[2] += f.x; acc[3] += f.y;
}

// 2 warps per node: warp-half h owns columns [h*128, (h+1)*128).
// Each lane owns 4 halves: cbase = h*128 + lane*4  (32 lanes x 4 = 128 cols).
__global__ void agg2_gather_kernel(const int* __restrict__ off,
                                   const int* __restrict__ csr_src,
                                   const __half* __restrict__ y,
                                   const float* __restrict__ inorm,
                                   const float* __restrict__ b2,
                                   float* __restrict__ out) {
    int gid = blockIdx.x * blockDim.x + threadIdx.x;
    int n = gid >> 6;
    if (n >= NN) return;
    int half = (gid >> 5) & 1;
    int lane = threadIdx.x & 31;
    int cbase = half * 128 + lane * 4;    // this thread's 4 halves
    int beg = off[n], end = off[n + 1];
    float acc[4] = {0.f, 0.f, 0.f, 0.f};
    for (int j = beg; j < end; j += 32) {
        int m = min(32, end - j);
        int s = (lane < m) ? __ldg(&csr_src[j + lane]) : 0;
        int k = 0;
        for (; k + 4 <= m; k += 4) {
            int s0 = __shfl_sync(0xffffffffu, s, k + 0);
            int s1 = __shfl_sync(0xffffffffu, s, k + 1);
            int s2 = __shfl_sync(0xffffffffu, s, k + 2);
            int s3 = __shfl_sync(0xffffffffu, s, k + 3);
            uint2 u0 = __ldg((const uint2*)(y + (size_t)s0 * FOUT + cbase));
            uint2 u1 = __ldg((const uint2*)(y + (size_t)s1 * FOUT + cbase));
            uint2 u2 = __ldg((const uint2*)(y + (size_t)s2 * FOUT + cbase));
            uint2 u3 = __ldg((const uint2*)(y + (size_t)s3 * FOUT + cbase));
            acc4(acc, u0); acc4(acc, u1); acc4(acc, u2); acc4(acc, u3);
        }
        for (; k < m; k++) {
            int ss = __shfl_sync(0xffffffffu, s, k);
            uint2 u = __ldg((const uint2*)(y + (size_t)ss * FOUT + cbase));
            acc4(acc, u);
        }
    }
    float sc = __ldg(&inorm[n]);
    float4 bb = *(const float4*)(b2 + cbase);
    float4 o;
    o.x = acc[0] * sc + bb.x;
    o.y = acc[1] * sc + bb.y;
    o.z = acc[2] * sc + bb.z;
    o.w = acc[3] * sc + bb.w;
    *(float4*)(out + (size_t)n * FOUT + cbase) = o;
}

// ----------------------------- fp16 tensor GEMM (cp.async, BK=64) ------------
// (round-8 proven version, unchanged)
#define ROWH 72
#define GEMM_SMEM ((2 * 128 * ROWH + 2 * 64 * ROWH) * 2)

template<bool RELU, bool HAS_BIAS>
__global__ __launch_bounds__(256)
void gemm_f16_kernel(const __half* __restrict__ A, const __half* __restrict__ Bt,
                     __half* __restrict__ C,
                     const float* __restrict__ rowscale,
                     const float* __restrict__ bias,
                     int M, int N, int K) {
    constexpr int BK = 64;
    extern __shared__ __align__(16) __half dynsmem[];
    __half* As = dynsmem;
    __half* Bs = dynsmem + 2 * 128 * ROWH;

    const int tid  = threadIdx.x;
    const int warp = tid >> 5;
    const int lane = tid & 31;
    const int wm = warp & 3;
    const int wn = warp >> 2;
    const int quad = lane >> 3;
    const int qr   = lane & 7;

    const int brow0 = blockIdx.y * 128;
    const int bcol0 = blockIdx.x * 64;

    const int st_c8 = tid & 7;
    const int st_r  = tid >> 3;

    unsigned as_base = (unsigned)__cvta_generic_to_shared(As);
    unsigned bs_base = (unsigned)__cvta_generic_to_shared(Bs);

    unsigned a_off[2], b_off[2];
#pragma unroll
    for (int mt = 0; mt < 2; mt++) {
        int row = wm * 32 + mt * 16 + qr + (quad & 1) * 8;
        a_off[mt] = (unsigned)((row * ROWH + (quad >> 1) * 8) * 2);
    }
#pragma unroll
    for (int ntp = 0; ntp < 2; ntp++) {
        int row = wn * 32 + ntp * 16 + (quad >> 1) * 8 + qr;
        b_off[ntp] = (unsigned)((row * ROWH + (quad & 1) * 8) * 2);
    }

    float acc[2][4][4];
#pragma unroll
    for (int mt = 0; mt < 2; mt++)
#pragma unroll
        for (int nt = 0; nt < 4; nt++)
#pragma unroll
            for (int f = 0; f < 4; f++) acc[mt][nt][f] = 0.f;

    auto stage = [&](int k0, int buf) {
#pragma unroll
        for (int l = 0; l < 4; l++) {
            int row = st_r + l * 32;
            int grow = brow0 + row;
            unsigned dst = as_base + (unsigned)((buf * 128 * ROWH + row * ROWH + st_c8 * 8) * 2);
            const __half* src = A + (size_t)grow * K + k0 + st_c8 * 8;
            cp16(dst, src, (grow < M) ? 16 : 0);
        }
#pragma unroll
        for (int l = 0; l < 2; l++) {
            int row = st_r + l * 32;
            unsigned dst = bs_base + (unsigned)((buf * 64 * ROWH + row * ROWH + st_c8 * 8) * 2);
            const __half* src = Bt + (size_t)(bcol0 + row) * K + k0 + st_c8 * 8;
            cp16(dst, src, 16);
        }
        cp_commit();
    };

    stage(0, 0);
    int buf = 0;
    const int KT = K / BK;

    for (int kt = 0; kt < KT; kt++) {
        if (kt + 1 < KT) {
            stage((kt + 1) * BK, buf ^ 1);
            cp_wait<1>();
        } else {
            cp_wait<0>();
        }
        __syncthreads();

        unsigned abuf = as_base + (unsigned)(buf * 128 * ROWH * 2);
        unsigned bbuf = bs_base + (unsigned)(buf * 64 * ROWH * 2);
#pragma unroll
        for (int ks = 0; ks < 4; ks++) {
            unsigned a[2][4], b[2][4];
#pragma unroll
            for (int mt = 0; mt < 2; mt++)
                ldsm_x4(a[mt][0], a[mt][1], a[mt][2], a[mt][3],
                        abuf + a_off[mt] + ks * 32);
#pragma unroll
            for (int ntp = 0; ntp < 2; ntp++)
                ldsm_x4(b[ntp][0], b[ntp][1], b[ntp][2], b[ntp][3],
                        bbuf + b_off[ntp] + ks * 32);
#pragma unroll
            for (int mt = 0; mt < 2; mt++)
#pragma unroll
                for (int nt = 0; nt < 4; nt++) {
                    unsigned b0 = b[nt >> 1][(nt & 1) * 2 + 0];
                    unsigned b1 = b[nt >> 1][(nt & 1) * 2 + 1];
                    mma_f16(acc[mt][nt][0], acc[mt][nt][1],
                            acc[mt][nt][2], acc[mt][nt][3],
                            a[mt][0], a[mt][1], a[mt][2], a[mt][3], b0, b1);
                }
        }
        __syncthreads();
        buf ^= 1;
    }

    const int gid = lane >> 2;
    const int tig = lane & 3;
#pragma unroll
    for (int mt = 0; mt < 2; mt++) {
        int r0 = brow0 + wm * 32 + mt * 16 + gid;
        int r1 = r0 + 8;
        float rs0 = (r0 < M) ? __ldg(&rowscale[r0]) : 0.f;
        float rs1 = (r1 < M) ? __ldg(&rowscale[r1]) : 0.f;
#pragma unroll
        for (int nt = 0; nt < 4; nt++) {
            int c = bcol0 + wn * 32 + nt * 8 + 2 * tig;
            float2 bb = make_float2(0.f, 0.f);
            if (HAS_BIAS) bb = *(const float2*)(bias + c);
            float2 o0, o1;
            o0.x = acc[mt][nt][0] * rs0 + bb.x;
            o0.y = acc[mt][nt][1] * rs0 + bb.y;
            o1.x = acc[mt][nt][2] * rs1 + bb.x;
            o1.y = acc[mt][nt][3] * rs1 + bb.y;
            if (RELU) {
                o0.x = fmaxf(o0.x, 0.f); o0.y = fmaxf(o0.y, 0.f);
                o1.x = fmaxf(o1.x, 0.f); o1.y = fmaxf(o1.y, 0.f);
            }
            if (r0 < M) *(__half2*)(C + (size_t)r0 * N + c) = __floats2half2_rn(o0.x, o0.y);
            if (r1 < M) *(__half2*)(C + (size_t)r1 * N + c) = __floats2half2_rn(o1.x, o1.y);
        }
    }
}

// ----------------------------- launch ---------------------------------------
extern "C" void kernel_launch(void* const* d_in, const int* in_sizes, int n_in,
                              void* d_out, int out_size) {
    const float *features = nullptr, *W1 = nullptr, *b1 = nullptr,
                *W2 = nullptr, *b2 = nullptr;
    const int* ei = nullptr;
    for (int i = 0; i < n_in; i++) {
        switch (in_sizes[i]) {
            case NN * FIN:      features = (const float*)d_in[i]; break;
            case FIN * FHID:    W1 = (const float*)d_in[i]; break;
            case FHID:          b1 = (const float*)d_in[i]; break;
            case FHID * FOUT:   W2 = (const float*)d_in[i]; break;
            case FOUT:          b2 = (const float*)d_in[i]; break;
            case 2 * NE:        ei = (const int*)d_in[i]; break;
            default: break;
        }
    }
    float* out = (float*)d_out;

    float *onorm, *inorm;
    __half *agg1h, *x1h, *y_h, *feat_h, *w1t, *w2t;
    int *deg, *off, *cursor, *csr_src, *incl, *bsum;
    cudaGetSymbolAddress((void**)&agg1h,   g_agg1h);
    cudaGetSymbolAddress((void**)&x1h,     g_x1h);
    cudaGetSymbolAddress((void**)&y_h,     g_y_h);
    cudaGetSymbolAddress((void**)&feat_h,  g_feat_h);
    cudaGetSymbolAddress((void**)&w1t,     g_w1t);
    cudaGetSymbolAddress((void**)&w2t,     g_w2t);
    cudaGetSymbolAddress((void**)&onorm,   g_out_norm);
    cudaGetSymbolAddress((void**)&inorm,   g_in_norm);
    cudaGetSymbolAddress((void**)&deg,     g_deg);
    cudaGetSymbolAddress((void**)&off,     g_off);
    cudaGetSymbolAddress((void**)&cursor,  g_cursor);
    cudaGetSymbolAddress((void**)&csr_src, g_csr_src);
    cudaGetSymbolAddress((void**)&incl,    g_incl);
    cudaGetSymbolAddress((void**)&bsum,    g_bsum);

    cudaFuncSetAttribute(gemm_f16_kernel<true, true>,
                         cudaFuncAttributeMaxDynamicSharedMemorySize, GEMM_SMEM);
    cudaFuncSetAttribute(gemm_f16_kernel<false, false>,
                         cudaFuncAttributeMaxDynamicSharedMemorySize, GEMM_SMEM);

    const int T = 256;

    cudaMemsetAsync(deg, 0, 2 * NN * sizeof(int));
    {
        dim3 b(32, 8);
        wtrans_kernel<<<dim3(FHID / 32, FIN / 32), b>>>(W1, w1t, FIN, FHID);
        wtrans_kernel<<<dim3(FOUT / 32, FHID / 32), b>>>(W2, w2t, FHID, FOUT);
    }
    degree_kernel<<<(NE + T - 1) / T, T>>>(ei, deg);
    scan1_kernel<<<NB, 256>>>(deg, incl, bsum);
    scan3_kernel<<<NB, 256>>>(deg, incl, bsum, off, cursor, onorm, inorm);
    scatter_f2h_kernel<<<(NE + T - 1) / T, T>>>(ei, cursor, csr_src,
                                                features, onorm, feat_h);
    {
        long long threads = (long long)NN * 32;
        agg1_gather_kernel<<<(unsigned)((threads + T - 1) / T), T>>>(
            off, csr_src, feat_h, agg1h);
    }
    {
        dim3 grid(FHID / 64, (NN + 127) / 128);
        gemm_f16_kernel<true, true><<<grid, 256, GEMM_SMEM>>>(
            agg1h, w1t, x1h, inorm, b1, NN, FHID, FIN);
    }
    {
        dim3 grid(FOUT / 64, (NN + 127) / 128);
        gemm_f16_kernel<false, false><<<grid, 256, GEMM_SMEM>>>(
            x1h, w2t, y_h, onorm, nullptr, NN, FOUT, FHID);
    }
    {
        long long threads = (long long)NN * 64;   // 2 warps per node
        agg2_gather_kernel<<<(unsigned)((threads + T - 1) / T), T>>>(
            off, csr_src, y_h, inorm, b2, out);
    }
}

// round 12
// speedup vs baseline: 2.4759x; 1.0227x over previous
#include <cuda_runtime.h>
#include <cuda_fp16.h>
#include <cstdint>

#define NN   50000
#define NE   800000
#define FIN  128
#define FHID 384
#define FOUT 256
#define NB   196          // ceil(NN/256) scan blocks

// ----------------------------- scratch --------------------------------------
__device__ __half g_agg1h[NN * FIN];             // 12.8 MB
__device__ __half g_x1h[(size_t)NN * FHID];      // 38.4 MB
__device__ __half g_y_h[(size_t)NN * FOUT];      // 25.6 MB
__device__ __half g_feat_h[NN * FIN];            // 12.8 MB (features * out_norm)
__device__ __half g_w1t[FHID * FIN];             // W1^T fp16 [384][128]
__device__ __half g_w2t[FOUT * FHID];            // W2^T fp16 [256][384]
__device__ int    g_deg[2 * NN];
__device__ float  g_out_norm[NN];
__device__ float  g_in_norm[NN];
__device__ int    g_off[NN + 1];
__device__ int    g_cursor[NN];
__device__ int    g_csr_src[NE];
__device__ int    g_incl[NN];
__device__ int    g_bsum[256];

// ----------------------------- helpers --------------------------------------
__device__ __forceinline__ void ldsm_x4(unsigned& r0, unsigned& r1,
                                        unsigned& r2, unsigned& r3, unsigned addr) {
    asm volatile("ldmatrix.sync.aligned.m8n8.x4.shared.b16 {%0,%1,%2,%3}, [%4];"
                 : "=r"(r0), "=r"(r1), "=r"(r2), "=r"(r3) : "r"(addr));
}

__device__ __forceinline__ void mma_f16(float& c0, float& c1, float& c2, float& c3,
                                        unsigned a0, unsigned a1, unsigned a2, unsigned a3,
                                        unsigned b0, unsigned b1) {
    asm volatile("mma.sync.aligned.m16n8k16.row.col.f32.f16.f16.f32 "
                 "{%0,%1,%2,%3}, {%4,%5,%6,%7}, {%8,%9}, {%0,%1,%2,%3};"
                 : "+f"(c0), "+f"(c1), "+f"(c2), "+f"(c3)
                 : "r"(a0), "r"(a1), "r"(a2), "r"(a3), "r"(b0), "r"(b1));
}

__device__ __forceinline__ void cp16(unsigned dst, const void* src, int src_sz) {
    asm volatile("cp.async.cg.shared.global [%0], [%1], 16, %2;"
                 :: "r"(dst), "l"(src), "r"(src_sz));
}
__device__ __forceinline__ void cp_commit() { asm volatile("cp.async.commit_group;"); }
template<int N_>
__device__ __forceinline__ void cp_wait() {
    asm volatile("cp.async.wait_group %0;" :: "n"(N_));
}
__device__ __forceinline__ __half2 bits2h(unsigned u) {
    return *reinterpret_cast<__half2*>(&u);
}

// ----------------------------- prelude kernels -------------------------------
__global__ void wtrans_kernel(const float* __restrict__ W, __half* __restrict__ Wt,
                              int R, int C) {
    __shared__ float tile[32][33];
    int bx = blockIdx.x * 32, by = blockIdx.y * 32;
    int x = bx + threadIdx.x;
#pragma unroll
    for (int i = 0; i < 32; i += 8) {
        int y = by + threadIdx.y + i;
        if (y < R && x < C) tile[threadIdx.y + i][threadIdx.x] = W[(size_t)y * C + x];
    }
    __syncthreads();
    int k = by + threadIdx.x;
#pragma unroll
    for (int i = 0; i < 32; i += 8) {
        int n = bx + threadIdx.y + i;
        if (n < C && k < R)
            Wt[(size_t)n * R + k] = __float2half(tile[threadIdx.x][threadIdx.y + i]);
    }
}

__global__ void degree_kernel(const int* __restrict__ ei, int* __restrict__ deg) {
    int e = blockIdx.x * blockDim.x + threadIdx.x;
    if (e < NE) {
        atomicAdd(&deg[ei[e]], 1);
        atomicAdd(&deg[NN + ei[NE + e]], 1);
    }
}

__global__ void scan1_kernel(const int* __restrict__ deg,
                             int* __restrict__ incl, int* __restrict__ bsum) {
    __shared__ int sh[256];
    int t = threadIdx.x;
    int i = blockIdx.x * 256 + t;
    int v = (i < NN) ? deg[NN + i] : 0;
    sh[t] = v;
    __syncthreads();
#pragma unroll
    for (int d = 1; d < 256; d <<= 1) {
        int x = (t >= d) ? sh[t - d] : 0;
        __syncthreads();
        if (t >= d) sh[t] += x;
        __syncthreads();
    }
    if (i < NN) incl[i] = sh[t];
    if (t == 255) bsum[blockIdx.x] = sh[255];
}

// scan3 with inlined block-prefix: each block sums bsum[0..bid)
__global__ void scan3_kernel(const int* __restrict__ deg,
                             const int* __restrict__ incl, const int* __restrict__ bsum,
                             int* __restrict__ off, int* __restrict__ cursor,
                             float* __restrict__ onorm, float* __restrict__ inorm) {
    __shared__ int sh[256];
    int t = threadIdx.x;
    sh[t] = (t < blockIdx.x && t < NB) ? bsum[t] : 0;
    __syncthreads();
#pragma unroll
    for (int d = 128; d > 0; d >>= 1) {
        if (t < d) sh[t] += sh[t + d];
        __syncthreads();
    }
    int bpre = sh[0];
    int i = blockIdx.x * 256 + t;
    if (i < NN) {
        int din = deg[NN + i];
        int excl = bpre + incl[i] - din;
        off[i] = excl;
        cursor[i] = excl;
        onorm[i] = rsqrtf((float)max(deg[i], 1));
        inorm[i] = rsqrtf((float)max(din, 1));
    }
    if (i == 0) off[NN] = NE;
}

__global__ void scatter_f2h_kernel(const int* __restrict__ ei,
                                   int* __restrict__ cursor,
                                   int* __restrict__ csr_src,
                                   const float* __restrict__ feat,
                                   const float* __restrict__ onorm,
                                   __half* __restrict__ feat_h) {
    int e = blockIdx.x * blockDim.x + threadIdx.x;
    if (e < NE) {
        int src = ei[e];
        int dst = ei[NE + e];
        int pos = atomicAdd(&cursor[dst], 1);
        csr_src[pos] = src;
    }
    const int n4 = NN * (FIN / 4);
    int total = blockDim.x * gridDim.x;
    for (int i = e; i < n4; i += total) {
        int row = i >> 5;
        float sc = __ldg(&onorm[row]);
        float4 v = ((const float4*)feat)[i];
        __half2 h0 = __floats2half2_rn(v.x * sc, v.y * sc);
        __half2 h1 = __floats2half2_rn(v.z * sc, v.w * sc);
        ((uint2*)feat_h)[i] = make_uint2(*(unsigned*)&h0, *(unsigned*)&h1);
    }
}

// ----------------------------- gathers ---------------------------------------
// Shared inner pattern: groups of 4 neighbors reduced with fp16 tree (3 HADD2
// per half2 slot), one fp32 flush per group; <4 tail stays exact fp32.

__global__ void agg1_gather_kernel(const int* __restrict__ off,
                                   const int* __restrict__ csr_src,
                                   const __half* __restrict__ feat,
                                   __half* __restrict__ aggh) {
    int n = (blockIdx.x * blockDim.x + threadIdx.x) >> 5;
    if (n >= NN) return;
    int lane = threadIdx.x & 31;
    int beg = off[n], end = off[n + 1];
    float4 acc = make_float4(0.f, 0.f, 0.f, 0.f);
    for (int j = beg; j < end; j += 32) {
        int m = min(32, end - j);
        int s = (lane < m) ? __ldg(&csr_src[j + lane]) : 0;
        int k = 0;
        for (; k + 4 <= m; k += 4) {
            int s0 = __shfl_sync(0xffffffffu, s, k + 0);
            int s1 = __shfl_sync(0xffffffffu, s, k + 1);
            int s2 = __shfl_sync(0xffffffffu, s, k + 2);
            int s3 = __shfl_sync(0xffffffffu, s, k + 3);
            uint2 u0 = __ldg((const uint2*)(feat + (size_t)s0 * FIN + lane * 4));
            uint2 u1 = __ldg((const uint2*)(feat + (size_t)s1 * FIN + lane * 4));
            uint2 u2 = __ldg((const uint2*)(feat + (size_t)s2 * FIN + lane * 4));
            uint2 u3 = __ldg((const uint2*)(feat + (size_t)s3 * FIN + lane * 4));
            // fp16 tree over 4 same-scale values, then fp32 flush
            __half2 ax = __hadd2(__hadd2(bits2h(u0.x), bits2h(u1.x)),
                                 __hadd2(bits2h(u2.x), bits2h(u3.x)));
            __half2 ay = __hadd2(__hadd2(bits2h(u0.y), bits2h(u1.y)),
                                 __hadd2(bits2h(u2.y), bits2h(u3.y)));
            float2 f0 = __half22float2(ax);
            float2 f1 = __half22float2(ay);
            acc.x += f0.x; acc.y += f0.y; acc.z += f1.x; acc.w += f1.y;
        }
        for (; k < m; k++) {
            int ss = __shfl_sync(0xffffffffu, s, k);
            uint2 u = __ldg((const uint2*)(feat + (size_t)ss * FIN + lane * 4));
            float2 a = __half22float2(bits2h(u.x));
            float2 b = __half22float2(bits2h(u.y));
            acc.x += a.x; acc.y += a.y; acc.z += b.x; acc.w += b.y;
        }
    }
    __half2 h0 = __floats2half2_rn(acc.x, acc.y);
    __half2 h1 = __floats2half2_rn(acc.z, acc.w);
    ((uint2*)(aggh + (size_t)n * FIN))[lane] = make_uint2(*(unsigned*)&h0, *(unsigned*)&h1);
}

// 2 warps per node: warp-half h owns columns [h*128, (h+1)*128), lane*4 halves.
__global__ void agg2_gather_kernel(const int* __restrict__ off,
                                   const int* __restrict__ csr_src,
                                   const __half* __restrict__ y,
                                   const float* __restrict__ inorm,
                                   const float* __restrict__ b2,
                                   float* __restrict__ out) {
    int gid = blockIdx.x * blockDim.x + threadIdx.x;
    int n = gid >> 6;
    if (n >= NN) return;
    int half = (gid >> 5) & 1;
    int lane = threadIdx.x & 31;
    int cbase = half * 128 + lane * 4;    // this thread's 4 halves
    int beg = off[n], end = off[n + 1];
    float acc[4] = {0.f, 0.f, 0.f, 0.f};
    for (int j = beg; j < end; j += 32) {
        int m = min(32, end - j);
        int s = (lane < m) ? __ldg(&csr_src[j + lane]) : 0;
        int k = 0;
        for (; k + 4 <= m; k += 4) {
            int s0 = __shfl_sync(0xffffffffu, s, k + 0);
            int s1 = __shfl_sync(0xffffffffu, s, k + 1);
            int s2 = __shfl_sync(0xffffffffu, s, k + 2);
            int s3 = __shfl_sync(0xffffffffu, s, k + 3);
            uint2 u0 = __ldg((const uint2*)(y + (size_t)s0 * FOUT + cbase));
            uint2 u1 = __ldg((const uint2*)(y + (size_t)s1 * FOUT + cbase));
            uint2 u2 = __ldg((const uint2*)(y + (size_t)s2 * FOUT + cbase));
            uint2 u3 = __ldg((const uint2*)(y + (size_t)s3 * FOUT + cbase));
            __half2 ax = __hadd2(__hadd2(bits2h(u0.x), bits2h(u1.x)),
                                 __hadd2(bits2h(u2.x), bits2h(u3.x)));
            __half2 ay = __hadd2(__hadd2(bits2h(u0.y), bits2h(u1.y)),
                                 __hadd2(bits2h(u2.y), bits2h(u3.y)));
            float2 f0 = __half22float2(ax);
            float2 f1 = __half22float2(ay);
            acc[0] += f0.x; acc[1] += f0.y; acc[2] += f1.x; acc[3] += f1.y;
        }
        for (; k < m; k++) {
            int ss = __shfl_sync(0xffffffffu, s, k);
            uint2 u = __ldg((const uint2*)(y + (size_t)ss * FOUT + cbase));
            float2 f0 = __half22float2(bits2h(u.x));
            float2 f1 = __half22float2(bits2h(u.y));
            acc[0] += f0.x; acc[1] += f0.y; acc[2] += f1.x; acc[3] += f1.y;
        }
    }
    float sc = __ldg(&inorm[n]);
    float4 bb = *(const float4*)(b2 + cbase);
    float4 o;
    o.x = acc[0] * sc + bb.x;
    o.y = acc[1] * sc + bb.y;
    o.z = acc[2] * sc + bb.z;
    o.w = acc[3] * sc + bb.w;
    *(float4*)(out + (size_t)n * FOUT + cbase) = o;
}

// ----------------------------- fp16 tensor GEMM (cp.async, BK=64) ------------
// (round-8/11 proven version, unchanged)
#define ROWH 72
#define GEMM_SMEM ((2 * 128 * ROWH + 2 * 64 * ROWH) * 2)

template<bool RELU, bool HAS_BIAS>
__global__ __launch_bounds__(256)
void gemm_f16_kernel(const __half* __restrict__ A, const __half* __restrict__ Bt,
                     __half* __restrict__ C,
                     const float* __restrict__ rowscale,
                     const float* __restrict__ bias,
                     int M, int N, int K) {
    constexpr int BK = 64;
    extern __shared__ __align__(16) __half dynsmem[];
    __half* As = dynsmem;
    __half* Bs = dynsmem + 2 * 128 * ROWH;

    const int tid  = threadIdx.x;
    const int warp = tid >> 5;
    const int lane = tid & 31;
    const int wm = warp & 3;
    const int wn = warp >> 2;
    const int quad = lane >> 3;
    const int qr   = lane & 7;

    const int brow0 = blockIdx.y * 128;
    const int bcol0 = blockIdx.x * 64;

    const int st_c8 = tid & 7;
    const int st_r  = tid >> 3;

    unsigned as_base = (unsigned)__cvta_generic_to_shared(As);
    unsigned bs_base = (unsigned)__cvta_generic_to_shared(Bs);

    unsigned a_off[2], b_off[2];
#pragma unroll
    for (int mt = 0; mt < 2; mt++) {
        int row = wm * 32 + mt * 16 + qr + (quad & 1) * 8;
        a_off[mt] = (unsigned)((row * ROWH + (quad >> 1) * 8) * 2);
    }
#pragma unroll
    for (int ntp = 0; ntp < 2; ntp++) {
        int row = wn * 32 + ntp * 16 + (quad >> 1) * 8 + qr;
        b_off[ntp] = (unsigned)((row * ROWH + (quad & 1) * 8) * 2);
    }

    float acc[2][4][4];
#pragma unroll
    for (int mt = 0; mt < 2; mt++)
#pragma unroll
        for (int nt = 0; nt < 4; nt++)
#pragma unroll
            for (int f = 0; f < 4; f++) acc[mt][nt][f] = 0.f;

    auto stage = [&](int k0, int buf) {
#pragma unroll
        for (int l = 0; l < 4; l++) {
            int row = st_r + l * 32;
            int grow = brow0 + row;
            unsigned dst = as_base + (unsigned)((buf * 128 * ROWH + row * ROWH + st_c8 * 8) * 2);
            const __half* src = A + (size_t)grow * K + k0 + st_c8 * 8;
            cp16(dst, src, (grow < M) ? 16 : 0);
        }
#pragma unroll
        for (int l = 0; l < 2; l++) {
            int row = st_r + l * 32;
            unsigned dst = bs_base + (unsigned)((buf * 64 * ROWH + row * ROWH + st_c8 * 8) * 2);
            const __half* src = Bt + (size_t)(bcol0 + row) * K + k0 + st_c8 * 8;
            cp16(dst, src, 16);
        }
        cp_commit();
    };

    stage(0, 0);
    int buf = 0;
    const int KT = K / BK;

    for (int kt = 0; kt < KT; kt++) {
        if (kt + 1 < KT) {
            stage((kt + 1) * BK, buf ^ 1);
            cp_wait<1>();
        } else {
            cp_wait<0>();
        }
        __syncthreads();

        unsigned abuf = as_base + (unsigned)(buf * 128 * ROWH * 2);
        unsigned bbuf = bs_base + (unsigned)(buf * 64 * ROWH * 2);
#pragma unroll
        for (int ks = 0; ks < 4; ks++) {
            unsigned a[2][4], b[2][4];
#pragma unroll
            for (int mt = 0; mt < 2; mt++)
                ldsm_x4(a[mt][0], a[mt][1], a[mt][2], a[mt][3],
                        abuf + a_off[mt] + ks * 32);
#pragma unroll
            for (int ntp = 0; ntp < 2; ntp++)
                ldsm_x4(b[ntp][0], b[ntp][1], b[ntp][2], b[ntp][3],
                        bbuf + b_off[ntp] + ks * 32);
#pragma unroll
            for (int mt = 0; mt < 2; mt++)
#pragma unroll
                for (int nt = 0; nt < 4; nt++) {
                    unsigned b0 = b[nt >> 1][(nt & 1) * 2 + 0];
                    unsigned b1 = b[nt >> 1][(nt & 1) * 2 + 1];
                    mma_f16(acc[mt][nt][0], acc[mt][nt][1],
                            acc[mt][nt][2], acc[mt][nt][3],
                            a[mt][0], a[mt][1], a[mt][2], a[mt][3], b0, b1);
                }
        }
        __syncthreads();
        buf ^= 1;
    }

    const int gid = lane >> 2;
    const int tig = lane & 3;
#pragma unroll
    for (int mt = 0; mt < 2; mt++) {
        int r0 = brow0 + wm * 32 + mt * 16 + gid;
        int r1 = r0 + 8;
        float rs0 = (r0 < M) ? __ldg(&rowscale[r0]) : 0.f;
        float rs1 = (r1 < M) ? __ldg(&rowscale[r1]) : 0.f;
#pragma unroll
        for (int nt = 0; nt < 4; nt++) {
            int c = bcol0 + wn * 32 + nt * 8 + 2 * tig;
            float2 bb = make_float2(0.f, 0.f);
            if (HAS_BIAS) bb = *(const float2*)(bias + c);
            float2 o0, o1;
            o0.x = acc[mt][nt][0] * rs0 + bb.x;
            o0.y = acc[mt][nt][1] * rs0 + bb.y;
            o1.x = acc[mt][nt][2] * rs1 + bb.x;
            o1.y = acc[mt][nt][3] * rs1 + bb.y;
            if (RELU) {
                o0.x = fmaxf(o0.x, 0.f); o0.y = fmaxf(o0.y, 0.f);
                o1.x = fmaxf(o1.x, 0.f); o1.y = fmaxf(o1.y, 0.f);
            }
            if (r0 < M) *(__half2*)(C + (size_t)r0 * N + c) = __floats2half2_rn(o0.x, o0.y);
            if (r1 < M) *(__half2*)(C + (size_t)r1 * N + c) = __floats2half2_rn(o1.x, o1.y);
        }
    }
}

// ----------------------------- launch ---------------------------------------
extern "C" void kernel_launch(void* const* d_in, const int* in_sizes, int n_in,
                              void* d_out, int out_size) {
    const float *features = nullptr, *W1 = nullptr, *b1 = nullptr,
                *W2 = nullptr, *b2 = nullptr;
    const int* ei = nullptr;
    for (int i = 0; i < n_in; i++) {
        switch (in_sizes[i]) {
            case NN * FIN:      features = (const float*)d_in[i]; break;
            case FIN * FHID:    W1 = (const float*)d_in[i]; break;
            case FHID:          b1 = (const float*)d_in[i]; break;
            case FHID * FOUT:   W2 = (const float*)d_in[i]; break;
            case FOUT:          b2 = (const float*)d_in[i]; break;
            case 2 * NE:        ei = (const int*)d_in[i]; break;
            default: break;
        }
    }
    float* out = (float*)d_out;

    float *onorm, *inorm;
    __half *agg1h, *x1h, *y_h, *feat_h, *w1t, *w2t;
    int *deg, *off, *cursor, *csr_src, *incl, *bsum;
    cudaGetSymbolAddress((void**)&agg1h,   g_agg1h);
    cudaGetSymbolAddress((void**)&x1h,     g_x1h);
    cudaGetSymbolAddress((void**)&y_h,     g_y_h);
    cudaGetSymbolAddress((void**)&feat_h,  g_feat_h);
    cudaGetSymbolAddress((void**)&w1t,     g_w1t);
    cudaGetSymbolAddress((void**)&w2t,     g_w2t);
    cudaGetSymbolAddress((void**)&onorm,   g_out_norm);
    cudaGetSymbolAddress((void**)&inorm,   g_in_norm);
    cudaGetSymbolAddress((void**)&deg,     g_deg);
    cudaGetSymbolAddress((void**)&off,     g_off);
    cudaGetSymbolAddress((void**)&cursor,  g_cursor);
    cudaGetSymbolAddress((void**)&csr_src, g_csr_src);
    cudaGetSymbolAddress((void**)&incl,    g_incl);
    cudaGetSymbolAddress((void**)&bsum,    g_bsum);

    cudaFuncSetAttribute(gemm_f16_kernel<true, true>,
                         cudaFuncAttributeMaxDynamicSharedMemorySize, GEMM_SMEM);
    cudaFuncSetAttribute(gemm_f16_kernel<false, false>,
                         cudaFuncAttributeMaxDynamicSharedMemorySize, GEMM_SMEM);

    const int T = 256;

    cudaMemsetAsync(deg, 0, 2 * NN * sizeof(int));
    {
        dim3 b(32, 8);
        wtrans_kernel<<<dim3(FHID / 32, FIN / 32), b>>>(W1, w1t, FIN, FHID);
        wtrans_kernel<<<dim3(FOUT / 32, FHID / 32), b>>>(W2, w2t, FHID, FOUT);
    }
    degree_kernel<<<(NE + T - 1) / T, T>>>(ei, deg);
    scan1_kernel<<<NB, 256>>>(deg, incl, bsum);
    scan3_kernel<<<NB, 256>>>(deg, incl, bsum, off, cursor, onorm, inorm);
    scatter_f2h_kernel<<<(NE + T - 1) / T, T>>>(ei, cursor, csr_src,
                                                features, onorm, feat_h);
    {
        long long threads = (long long)NN * 32;
        agg1_gather_kernel<<<(unsigned)((threads + T - 1) / T), T>>>(
            off, csr_src, feat_h, agg1h);
    }
    {
        dim3 grid(FHID / 64, (NN + 127) / 128);
        gemm_f16_kernel<true, true><<<grid, 256, GEMM_SMEM>>>(
            agg1h, w1t, x1h, inorm, b1, NN, FHID, FIN);
    }
    {
        dim3 grid(FOUT / 64, (NN + 127) / 128);
        gemm_f16_kernel<false, false><<<grid, 256, GEMM_SMEM>>>(
            x1h, w2t, y_h, onorm, nullptr, NN, FOUT, FHID);
    }
    {
        long long threads = (long long)NN * 64;   // 2 warps per node
        agg2_gather_kernel<<<(unsigned)((threads + T - 1) / T), T>>>(
            off, csr_src, y_h, inorm, b2, out);
    }
}

// round 13
// speedup vs baseline: 2.4807x; 1.0019x over previous
#include <cuda_runtime.h>
#include <cuda_fp16.h>
#include <cstdint>

#define NN   50000
#define NE   800000
#define FIN  128
#define FHID 384
#define FOUT 256
#define NB   196          // ceil(NN/256) scan blocks

// ----------------------------- scratch --------------------------------------
__device__ __half g_agg1h[NN * FIN];             // 12.8 MB
__device__ __half g_x1h[(size_t)NN * FHID];      // 38.4 MB
__device__ __half g_y_h[(size_t)NN * FOUT];      // 25.6 MB
__device__ __half g_feat_h[NN * FIN];            // 12.8 MB (features * out_norm)
__device__ __half g_w1t[FHID * FIN];             // W1^T fp16 [384][128]
__device__ __half g_w2t[FOUT * FHID];            // W2^T fp16 [256][384]
__device__ int    g_deg[2 * NN];
__device__ float  g_out_norm[NN];
__device__ float  g_in_norm[NN];
__device__ int    g_off[NN + 1];
__device__ int    g_cursor[NN];
__device__ int    g_csr_src[NE];
__device__ int    g_incl[NN];
__device__ int    g_bsum[256];

// ----------------------------- helpers --------------------------------------
__device__ __forceinline__ void ldsm_x4(unsigned& r0, unsigned& r1,
                                        unsigned& r2, unsigned& r3, unsigned addr) {
    asm volatile("ldmatrix.sync.aligned.m8n8.x4.shared.b16 {%0,%1,%2,%3}, [%4];"
                 : "=r"(r0), "=r"(r1), "=r"(r2), "=r"(r3) : "r"(addr));
}

__device__ __forceinline__ void mma_f16(float& c0, float& c1, float& c2, float& c3,
                                        unsigned a0, unsigned a1, unsigned a2, unsigned a3,
                                        unsigned b0, unsigned b1) {
    asm volatile("mma.sync.aligned.m16n8k16.row.col.f32.f16.f16.f32 "
                 "{%0,%1,%2,%3}, {%4,%5,%6,%7}, {%8,%9}, {%0,%1,%2,%3};"
                 : "+f"(c0), "+f"(c1), "+f"(c2), "+f"(c3)
                 : "r"(a0), "r"(a1), "r"(a2), "r"(a3), "r"(b0), "r"(b1));
}

__device__ __forceinline__ void cp16(unsigned dst, const void* src, int src_sz) {
    asm volatile("cp.async.cg.shared.global [%0], [%1], 16, %2;"
                 :: "r"(dst), "l"(src), "r"(src_sz));
}
__device__ __forceinline__ void cp_commit() { asm volatile("cp.async.commit_group;"); }
template<int N_>
__device__ __forceinline__ void cp_wait() {
    asm volatile("cp.async.wait_group %0;" :: "n"(N_));
}
__device__ __forceinline__ __half2 bits2h(unsigned u) {
    return *reinterpret_cast<__half2*>(&u);
}

// ----------------------------- prelude kernels -------------------------------
__global__ void wtrans_kernel(const float* __restrict__ W, __half* __restrict__ Wt,
                              int R, int C) {
    __shared__ float tile[32][33];
    int bx = blockIdx.x * 32, by = blockIdx.y * 32;
    int x = bx + threadIdx.x;
#pragma unroll
    for (int i = 0; i < 32; i += 8) {
        int y = by + threadIdx.y + i;
        if (y < R && x < C) tile[threadIdx.y + i][threadIdx.x] = W[(size_t)y * C + x];
    }
    __syncthreads();
    int k = by + threadIdx.x;
#pragma unroll
    for (int i = 0; i < 32; i += 8) {
        int n = bx + threadIdx.y + i;
        if (n < C && k < R)
            Wt[(size_t)n * R + k] = __float2half(tile[threadIdx.x][threadIdx.y + i]);
    }
}

// 4 edges per thread via int4 loads (NE % 4 == 0)
__global__ void degree_kernel(const int* __restrict__ ei, int* __restrict__ deg) {
    int q = blockIdx.x * blockDim.x + threadIdx.x;
    if (q < NE / 4) {
        int4 s = ((const int4*)ei)[q];
        int4 d = ((const int4*)(ei + NE))[q];
        atomicAdd(&deg[s.x], 1); atomicAdd(&deg[s.y], 1);
        atomicAdd(&deg[s.z], 1); atomicAdd(&deg[s.w], 1);
        atomicAdd(&deg[NN + d.x], 1); atomicAdd(&deg[NN + d.y], 1);
        atomicAdd(&deg[NN + d.z], 1); atomicAdd(&deg[NN + d.w], 1);
    }
}

__global__ void scan1_kernel(const int* __restrict__ deg,
                             int* __restrict__ incl, int* __restrict__ bsum) {
    __shared__ int sh[256];
    int t = threadIdx.x;
    int i = blockIdx.x * 256 + t;
    int v = (i < NN) ? deg[NN + i] : 0;
    sh[t] = v;
    __syncthreads();
#pragma unroll
    for (int d = 1; d < 256; d <<= 1) {
        int x = (t >= d) ? sh[t - d] : 0;
        __syncthreads();
        if (t >= d) sh[t] += x;
        __syncthreads();
    }
    if (i < NN) incl[i] = sh[t];
    if (t == 255) bsum[blockIdx.x] = sh[255];
}

// scan3 with inlined block-prefix: each block sums bsum[0..bid)
__global__ void scan3_kernel(const int* __restrict__ deg,
                             const int* __restrict__ incl, const int* __restrict__ bsum,
                             int* __restrict__ off, int* __restrict__ cursor,
                             float* __restrict__ onorm, float* __restrict__ inorm) {
    __shared__ int sh[256];
    int t = threadIdx.x;
    sh[t] = (t < blockIdx.x && t < NB) ? bsum[t] : 0;
    __syncthreads();
#pragma unroll
    for (int d = 128; d > 0; d >>= 1) {
        if (t < d) sh[t] += sh[t + d];
        __syncthreads();
    }
    int bpre = sh[0];
    int i = blockIdx.x * 256 + t;
    if (i < NN) {
        int din = deg[NN + i];
        int excl = bpre + incl[i] - din;
        off[i] = excl;
        cursor[i] = excl;
        onorm[i] = rsqrtf((float)max(deg[i], 1));
        inorm[i] = rsqrtf((float)max(din, 1));
    }
    if (i == 0) off[NN] = NE;
}

// 4 edges per thread; f2h grid-stride piggyback unchanged
__global__ void scatter_f2h_kernel(const int* __restrict__ ei,
                                   int* __restrict__ cursor,
                                   int* __restrict__ csr_src,
                                   const float* __restrict__ feat,
                                   const float* __restrict__ onorm,
                                   __half* __restrict__ feat_h) {
    int q = blockIdx.x * blockDim.x + threadIdx.x;
    if (q < NE / 4) {
        int4 s = ((const int4*)ei)[q];
        int4 d = ((const int4*)(ei + NE))[q];
        csr_src[atomicAdd(&cursor[d.x], 1)] = s.x;
        csr_src[atomicAdd(&cursor[d.y], 1)] = s.y;
        csr_src[atomicAdd(&cursor[d.z], 1)] = s.z;
        csr_src[atomicAdd(&cursor[d.w], 1)] = s.w;
    }
    const int n4 = NN * (FIN / 4);
    int total = blockDim.x * gridDim.x;
    for (int i = q; i < n4; i += total) {
        int row = i >> 5;
        float sc = __ldg(&onorm[row]);
        float4 v = ((const float4*)feat)[i];
        __half2 h0 = __floats2half2_rn(v.x * sc, v.y * sc);
        __half2 h1 = __floats2half2_rn(v.z * sc, v.w * sc);
        ((uint2*)feat_h)[i] = make_uint2(*(unsigned*)&h0, *(unsigned*)&h1);
    }
}

// ----------------------------- gathers ---------------------------------------
__global__ void agg1_gather_kernel(const int* __restrict__ off,
                                   const int* __restrict__ csr_src,
                                   const __half* __restrict__ feat,
                                   __half* __restrict__ aggh) {
    int n = (blockIdx.x * blockDim.x + threadIdx.x) >> 5;
    if (n >= NN) return;
    int lane = threadIdx.x & 31;
    int beg = off[n], end = off[n + 1];
    float4 acc = make_float4(0.f, 0.f, 0.f, 0.f);
    for (int j = beg; j < end; j += 32) {
        int m = min(32, end - j);
        int s = (lane < m) ? __ldg(&csr_src[j + lane]) : 0;
        int k = 0;
        for (; k + 4 <= m; k += 4) {
            int s0 = __shfl_sync(0xffffffffu, s, k + 0);
            int s1 = __shfl_sync(0xffffffffu, s, k + 1);
            int s2 = __shfl_sync(0xffffffffu, s, k + 2);
            int s3 = __shfl_sync(0xffffffffu, s, k + 3);
            uint2 u0 = __ldg((const uint2*)(feat + (size_t)s0 * FIN + lane * 4));
            uint2 u1 = __ldg((const uint2*)(feat + (size_t)s1 * FIN + lane * 4));
            uint2 u2 = __ldg((const uint2*)(feat + (size_t)s2 * FIN + lane * 4));
            uint2 u3 = __ldg((const uint2*)(feat + (size_t)s3 * FIN + lane * 4));
            __half2 ax = __hadd2(__hadd2(bits2h(u0.x), bits2h(u1.x)),
                                 __hadd2(bits2h(u2.x), bits2h(u3.x)));
            __half2 ay = __hadd2(__hadd2(bits2h(u0.y), bits2h(u1.y)),
                                 __hadd2(bits2h(u2.y), bits2h(u3.y)));
            float2 f0 = __half22float2(ax);
            float2 f1 = __half22float2(ay);
            acc.x += f0.x; acc.y += f0.y; acc.z += f1.x; acc.w += f1.y;
        }
        for (; k < m; k++) {
            int ss = __shfl_sync(0xffffffffu, s, k);
            uint2 u = __ldg((const uint2*)(feat + (size_t)ss * FIN + lane * 4));
            float2 a = __half22float2(bits2h(u.x));
            float2 b = __half22float2(bits2h(u.y));
            acc.x += a.x; acc.y += a.y; acc.z += b.x; acc.w += b.y;
        }
    }
    __half2 h0 = __floats2half2_rn(acc.x, acc.y);
    __half2 h1 = __floats2half2_rn(acc.z, acc.w);
    ((uint2*)(aggh + (size_t)n * FIN))[lane] = make_uint2(*(unsigned*)&h0, *(unsigned*)&h1);
}

// 2 warps per node: warp-half h owns columns [h*128, (h+1)*128), lane*4 halves.
__global__ void agg2_gather_kernel(const int* __restrict__ off,
                                   const int* __restrict__ csr_src,
                                   const __half* __restrict__ y,
                                   const float* __restrict__ inorm,
                                   const float* __restrict__ b2,
                                   float* __restrict__ out) {
    int gid = blockIdx.x * blockDim.x + threadIdx.x;
    int n = gid >> 6;
    if (n >= NN) return;
    int half = (gid >> 5) & 1;
    int lane = threadIdx.x & 31;
    int cbase = half * 128 + lane * 4;
    int beg = off[n], end = off[n + 1];
    float acc[4] = {0.f, 0.f, 0.f, 0.f};
    for (int j = beg; j < end; j += 32) {
        int m = min(32, end - j);
        int s = (lane < m) ? __ldg(&csr_src[j + lane]) : 0;
        int k = 0;
        for (; k + 4 <= m; k += 4) {
            int s0 = __shfl_sync(0xffffffffu, s, k + 0);
            int s1 = __shfl_sync(0xffffffffu, s, k + 1);
            int s2 = __shfl_sync(0xffffffffu, s, k + 2);
            int s3 = __shfl_sync(0xffffffffu, s, k + 3);
            uint2 u0 = __ldg((const uint2*)(y + (size_t)s0 * FOUT + cbase));
            uint2 u1 = __ldg((const uint2*)(y + (size_t)s1 * FOUT + cbase));
            uint2 u2 = __ldg((const uint2*)(y + (size_t)s2 * FOUT + cbase));
            uint2 u3 = __ldg((const uint2*)(y + (size_t)s3 * FOUT + cbase));
            __half2 ax = __hadd2(__hadd2(bits2h(u0.x), bits2h(u1.x)),
                                 __hadd2(bits2h(u2.x), bits2h(u3.x)));
            __half2 ay = __hadd2(__hadd2(bits2h(u0.y), bits2h(u1.y)),
                                 __hadd2(bits2h(u2.y), bits2h(u3.y)));
            float2 f0 = __half22float2(ax);
            float2 f1 = __half22float2(ay);
            acc[0] += f0.x; acc[1] += f0.y; acc[2] += f1.x; acc[3] += f1.y;
        }
        for (; k < m; k++) {
            int ss = __shfl_sync(0xffffffffu, s, k);
            uint2 u = __ldg((const uint2*)(y + (size_t)ss * FOUT + cbase));
            float2 f0 = __half22float2(bits2h(u.x));
            float2 f1 = __half22float2(bits2h(u.y));
            acc[0] += f0.x; acc[1] += f0.y; acc[2] += f1.x; acc[3] += f1.y;
        }
    }
    float sc = __ldg(&inorm[n]);
    float4 bb = *(const float4*)(b2 + cbase);
    float4 o;
    o.x = acc[0] * sc + bb.x;
    o.y = acc[1] * sc + bb.y;
    o.z = acc[2] * sc + bb.z;
    o.w = acc[3] * sc + bb.w;
    *(float4*)(out + (size_t)n * FOUT + cbase) = o;
}

// ----------------------------- fp16 tensor GEMM (cp.async, BM=128 BN=128 BK=64)
// C[M,N](fp16) = epi( (A[M,K] @ Bt[N,K]^T) * rowscale[row] (+bias) (relu) )
// 8 warps (4M x 2N), warp tile 32x64. Double-buffered cp.async staging.
#define ROWH 72
#define GEMM_SMEM ((2 * 128 * ROWH + 2 * 128 * ROWH) * 2)   // 72 KB

template<bool RELU, bool HAS_BIAS>
__global__ __launch_bounds__(256)
void gemm_f16_kernel(const __half* __restrict__ A, const __half* __restrict__ Bt,
                     __half* __restrict__ C,
                     const float* __restrict__ rowscale,
                     const float* __restrict__ bias,
                     int M, int N, int K) {
    constexpr int BK = 64;
    extern __shared__ __align__(16) __half dynsmem[];
    __half* As = dynsmem;                       // [2][128*ROWH]
    __half* Bs = dynsmem + 2 * 128 * ROWH;      // [2][128*ROWH]

    const int tid  = threadIdx.x;
    const int warp = tid >> 5;
    const int lane = tid & 31;
    const int wm = warp & 3;
    const int wn = warp >> 2;
    const int quad = lane >> 3;
    const int qr   = lane & 7;

    const int brow0 = blockIdx.y * 128;
    const int bcol0 = blockIdx.x * 128;

    const int st_c8 = tid & 7;
    const int st_r  = tid >> 3;    // 0..31

    unsigned as_base = (unsigned)__cvta_generic_to_shared(As);
    unsigned bs_base = (unsigned)__cvta_generic_to_shared(Bs);

    unsigned a_off[2], b_off[4];
#pragma unroll
    for (int mt = 0; mt < 2; mt++) {
        int row = wm * 32 + mt * 16 + qr + (quad & 1) * 8;
        a_off[mt] = (unsigned)((row * ROWH + (quad >> 1) * 8) * 2);
    }
#pragma unroll
    for (int ntp = 0; ntp < 4; ntp++) {
        int row = wn * 64 + ntp * 16 + (quad >> 1) * 8 + qr;
        b_off[ntp] = (unsigned)((row * ROWH + (quad & 1) * 8) * 2);
    }

    float acc[2][8][4];
#pragma unroll
    for (int mt = 0; mt < 2; mt++)
#pragma unroll
        for (int nt = 0; nt < 8; nt++)
#pragma unroll
            for (int f = 0; f < 4; f++) acc[mt][nt][f] = 0.f;

    auto stage = [&](int k0, int buf) {
#pragma unroll
        for (int l = 0; l < 4; l++) {
            int row = st_r + l * 32;
            int grow = brow0 + row;
            unsigned dst = as_base + (unsigned)((buf * 128 * ROWH + row * ROWH + st_c8 * 8) * 2);
            const __half* src = A + (size_t)grow * K + k0 + st_c8 * 8;
            cp16(dst, src, (grow < M) ? 16 : 0);
        }
#pragma unroll
        for (int l = 0; l < 4; l++) {
            int row = st_r + l * 32;
            unsigned dst = bs_base + (unsigned)((buf * 128 * ROWH + row * ROWH + st_c8 * 8) * 2);
            const __half* src = Bt + (size_t)(bcol0 + row) * K + k0 + st_c8 * 8;
            cp16(dst, src, 16);
        }
        cp_commit();
    };

    stage(0, 0);
    int buf = 0;
    const int KT = K / BK;

    for (int kt = 0; kt < KT; kt++) {
        if (kt + 1 < KT) {
            stage((kt + 1) * BK, buf ^ 1);
            cp_wait<1>();
        } else {
            cp_wait<0>();
        }
        __syncthreads();

        unsigned abuf = as_base + (unsigned)(buf * 128 * ROWH * 2);
        unsigned bbuf = bs_base + (unsigned)(buf * 128 * ROWH * 2);
#pragma unroll
        for (int ks = 0; ks < 4; ks++) {
            unsigned a[2][4], b[4][4];
#pragma unroll
            for (int mt = 0; mt < 2; mt++)
                ldsm_x4(a[mt][0], a[mt][1], a[mt][2], a[mt][3],
                        abuf + a_off[mt] + ks * 32);
#pragma unroll
            for (int ntp = 0; ntp < 4; ntp++)
                ldsm_x4(b[ntp][0], b[ntp][1], b[ntp][2], b[ntp][3],
                        bbuf + b_off[ntp] + ks * 32);
#pragma unroll
            for (int mt = 0; mt < 2; mt++)
#pragma unroll
                for (int nt = 0; nt < 8; nt++) {
                    unsigned b0 = b[nt >> 1][(nt & 1) * 2 + 0];
                    unsigned b1 = b[nt >> 1][(nt & 1) * 2 + 1];
                    mma_f16(acc[mt][nt][0], acc[mt][nt][1],
                            acc[mt][nt][2], acc[mt][nt][3],
                            a[mt][0], a[mt][1], a[mt][2], a[mt][3], b0, b1);
                }
        }
        __syncthreads();
        buf ^= 1;
    }

    const int gid = lane >> 2;
    const int tig = lane & 3;
#pragma unroll
    for (int mt = 0; mt < 2; mt++) {
        int r0 = brow0 + wm * 32 + mt * 16 + gid;
        int r1 = r0 + 8;
        float rs0 = (r0 < M) ? __ldg(&rowscale[r0]) : 0.f;
        float rs1 = (r1 < M) ? __ldg(&rowscale[r1]) : 0.f;
#pragma unroll
        for (int nt = 0; nt < 8; nt++) {
            int c = bcol0 + wn * 64 + nt * 8 + 2 * tig;
            float2 bb = make_float2(0.f, 0.f);
            if (HAS_BIAS) bb = *(const float2*)(bias + c);
            float2 o0, o1;
            o0.x = acc[mt][nt][0] * rs0 + bb.x;
            o0.y = acc[mt][nt][1] * rs0 + bb.y;
            o1.x = acc[mt][nt][2] * rs1 + bb.x;
            o1.y = acc[mt][nt][3] * rs1 + bb.y;
            if (RELU) {
                o0.x = fmaxf(o0.x, 0.f); o0.y = fmaxf(o0.y, 0.f);
                o1.x = fmaxf(o1.x, 0.f); o1.y = fmaxf(o1.y, 0.f);
            }
            if (r0 < M) *(__half2*)(C + (size_t)r0 * N + c) = __floats2half2_rn(o0.x, o0.y);
            if (r1 < M) *(__half2*)(C + (size_t)r1 * N + c) = __floats2half2_rn(o1.x, o1.y);
        }
    }
}

// ----------------------------- launch ---------------------------------------
extern "C" void kernel_launch(void* const* d_in, const int* in_sizes, int n_in,
                              void* d_out, int out_size) {
    const float *features = nullptr, *W1 = nullptr, *b1 = nullptr,
                *W2 = nullptr, *b2 = nullptr;
    const int* ei = nullptr;
    for (int i = 0; i < n_in; i++) {
        switch (in_sizes[i]) {
            case NN * FIN:      features = (const float*)d_in[i]; break;
            case FIN * FHID:    W1 = (const float*)d_in[i]; break;
            case FHID:          b1 = (const float*)d_in[i]; break;
            case FHID * FOUT:   W2 = (const float*)d_in[i]; break;
            case FOUT:          b2 = (const float*)d_in[i]; break;
            case 2 * NE:        ei = (const int*)d_in[i]; break;
            default: break;
        }
    }
    float* out = (float*)d_out;

    float *onorm, *inorm;
    __half *agg1h, *x1h, *y_h, *feat_h, *w1t, *w2t;
    int *deg, *off, *cursor, *csr_src, *incl, *bsum;
    cudaGetSymbolAddress((void**)&agg1h,   g_agg1h);
    cudaGetSymbolAddress((void**)&x1h,     g_x1h);
    cudaGetSymbolAddress((void**)&y_h,     g_y_h);
    cudaGetSymbolAddress((void**)&feat_h,  g_feat_h);
    cudaGetSymbolAddress((void**)&w1t,     g_w1t);
    cudaGetSymbolAddress((void**)&w2t,     g_w2t);
    cudaGetSymbolAddress((void**)&onorm,   g_out_norm);
    cudaGetSymbolAddress((void**)&inorm,   g_in_norm);
    cudaGetSymbolAddress((void**)&deg,     g_deg);
    cudaGetSymbolAddress((void**)&off,     g_off);
    cudaGetSymbolAddress((void**)&cursor,  g_cursor);
    cudaGetSymbolAddress((void**)&csr_src, g_csr_src);
    cudaGetSymbolAddress((void**)&incl,    g_incl);
    cudaGetSymbolAddress((void**)&bsum,    g_bsum);

    cudaFuncSetAttribute(gemm_f16_kernel<true, true>,
                         cudaFuncAttributeMaxDynamicSharedMemorySize, GEMM_SMEM);
    cudaFuncSetAttribute(gemm_f16_kernel<false, false>,
                         cudaFuncAttributeMaxDynamicSharedMemorySize, GEMM_SMEM);

    const int T = 256;

    cudaMemsetAsync(deg, 0, 2 * NN * sizeof(int));
    {
        dim3 b(32, 8);
        wtrans_kernel<<<dim3(FHID / 32, FIN / 32), b>>>(W1, w1t, FIN, FHID);
        wtrans_kernel<<<dim3(FOUT / 32, FHID / 32), b>>>(W2, w2t, FHID, FOUT);
    }
    degree_kernel<<<(NE / 4 + T - 1) / T, T>>>(ei, deg);
    scan1_kernel<<<NB, 256>>>(deg, incl, bsum);
    scan3_kernel<<<NB, 256>>>(deg, incl, bsum, off, cursor, onorm, inorm);
    scatter_f2h_kernel<<<(NE / 4 + T - 1) / T, T>>>(ei, cursor, csr_src,
                                                    features, onorm, feat_h);
    {
        long long threads = (long long)NN * 32;
        agg1_gather_kernel<<<(unsigned)((threads + T - 1) / T), T>>>(
            off, csr_src, feat_h, agg1h);
    }
    {
        dim3 grid(FHID / 128, (NN + 127) / 128);
        gemm_f16_kernel<true, true><<<grid, 256, GEMM_SMEM>>>(
            agg1h, w1t, x1h, inorm, b1, NN, FHID, FIN);
    }
    {
        dim3 grid(FOUT / 128, (NN + 127) / 128);
        gemm_f16_kernel<false, false><<<grid, 256, GEMM_SMEM>>>(
            x1h, w2t, y_h, onorm, nullptr, NN, FOUT, FHID);
    }
    {
        long long threads = (long long)NN * 64;   // 2 warps per node
        agg2_gather_kernel<<<(unsigned)((threads + T - 1) / T), T>>>(
            off, csr_src, y_h, inorm, b2, out);
    }
}